// round 14
// baseline (speedup 1.0000x reference)
#include <cuda_runtime.h>
#include <cuda_bf16.h>

#define CKD 128
typedef unsigned long long ull;

// ---------------- static scratch ----------------
__device__ float  g_xs[(long)16*8191*128];
__device__ float  g_d [(long)16*4096*128];
__device__ float  g_ud[(long)16*8191*128];
__device__ float  g_us[(long)16*8191*128];
__device__ float2 g_part[(long)2*16*16*64*128];
__device__ float2 g_ftd[16*64*128];
__device__ float2 g_ftx[16*64*128];
__device__ float2 g_oud[16*64*128];
__device__ float2 g_ous[16*64*128];
__device__ float2 g_wt[(long)3*64*128*128];
__device__ float2 g_tw[4096+64];
__device__ ulonglong2 g_ftw[(long)96*4096];

#define DEEP_FT_BASE 0L
#define DEEP_OU_BASE 1835008L

// ---------------- f32x2 helpers ----------------
__device__ __forceinline__ ull pk2(float x, float y){
    ull r; asm("mov.b64 %0, {%1, %2};" : "=l"(r) : "f"(x), "f"(y)); return r;
}
__device__ __forceinline__ float2 up2(ull v){
    float2 r; asm("mov.b64 {%0, %1}, %2;" : "=f"(r.x), "=f"(r.y) : "l"(v)); return r;
}
__device__ __forceinline__ void ffma2(ull &acc, ull a, ull b){
    asm("fma.rn.f32x2 %0, %1, %2, %0;" : "+l"(acc) : "l"(a), "l"(b));
}
__device__ __forceinline__ long off_level(int l){
    long o = 0; int nhf = 4096;
    for (int i=0;i<l;++i){ o += (long)16*nhf*128; nhf >>= 1; }
    return o;
}
__device__ __forceinline__ float2 twid(int r){
    float sn, cs;
    sincospif((float)r * (-1.0f/2048.0f), &sn, &cs);
    return make_float2(cs, sn);
}

// ---------------- base twiddle table (deep kernels) ----------------
__global__ void k_base(){
    int r = blockIdx.x*blockDim.x + threadIdx.x;
    if (r >= 4096) return;
    float s, c;
    sincospif(r/2048.0f, &s, &c);
    g_tw[r] = make_float2(c, -s);
    if (r < 64) g_tw[4096+r] = make_float2(0.f, 0.f);
}

// ---------------- batched packed twiddle tables for shallow levels 0..5 ----------------
__global__ void k_tw_all(){
    const int CUM[7] = {0, 196608, 294912, 344064, 368640, 380928, 387072};
    int idx = blockIdx.x*blockDim.x + threadIdx.x;
    if (idx >= 387072) return;
    int l = 0;
    #pragma unroll
    for (int i=1; i<6; ++i) if (idx >= CUM[i]) l = i;
    int local = idx - CUM[l];
    int n2 = 2048 >> l;
    int stride = 1 << l;
    int n = 4096 >> l;
    float invn = 1.0f / (float)n;
    long base = CUM[l];
    long nf = (long)32*n2;
    if (local < nf){
        int jj = local & 3;
        int r = local >> 2;
        int s = r % n2;
        int gh = r / n2;
        int me = (gh>>1)*16 + (gh&1)*8 + 2*jj;
        int mo = me + 1;
        float2 te = twid((me*s*stride)&4095);
        float2 to = twid((mo*s*stride)&4095);
        g_ftw[base + local] = make_ulonglong2(pk2(te.x,te.y), pk2(to.x,to.y));
    } else {
        int r = local - (int)nf;
        int m = r / n2;
        int t = r - m*n2;
        float2 e = twid((m*t*stride)&4095);
        float sc = (m==0) ? invn : 2.f*invn;
        g_ftw[base + local] = make_ulonglong2(pk2(sc*e.x, sc*e.x), pk2(sc*e.y, sc*e.y));
    }
}

// ---------------- weight transpose ----------------
__global__ void k_wtrans(const float* __restrict__ Ar, const float* __restrict__ Ai,
                         const float* __restrict__ Br, const float* __restrict__ Bi,
                         const float* __restrict__ Cr, const float* __restrict__ Ci){
    long gidx = blockIdx.x*(long)blockDim.x + threadIdx.x;
    const long per = (long)64*128*128;
    if (gidx >= 3*per) return;
    int mat = (int)(gidx / per);
    long idx = gidx - (long)mat*per;
    const float* wr = mat==0 ? Ar : (mat==1 ? Br : Cr);
    const float* wi = mat==0 ? Ai : (mat==1 ? Bi : Ci);
    int m = (int)(idx & 63);
    int o = (int)((idx >> 6) & 127);
    int i = (int)(idx >> 13);
    g_wt[((long)mat*64 + m)*16384 + (long)i*128 + o] = make_float2(wr[idx], wi[idx]);
}

// ---------------- wavelet decompose ----------------
__global__ void __launch_bounds__(256) k_decompose(const float* __restrict__ xext, long xoff,
        long soff, long doff,
        const float* __restrict__ ecs, const float* __restrict__ ecd, int nh){
    __shared__ ull f[128];
    if (threadIdx.x < 128) f[threadIdx.x] = pk2(ecs[threadIdx.x], ecd[threadIdx.x]);
    __syncthreads();
    long idx = blockIdx.x*(long)blockDim.x + threadIdx.x;
    if (idx >= (long)16*nh*16) return;
    int c = (int)(idx & 15);
    long bt = idx >> 4;
    const float* xin = xext ? xext : (g_xs + xoff);
    const float* pe = xin + bt*2*CKD + c*8;
    float4 e0 = *(const float4*)(pe);
    float4 e1 = *(const float4*)(pe+4);
    float4 o0 = *(const float4*)(pe+CKD);
    float4 o1 = *(const float4*)(pe+CKD+4);
    float xa[16] = {e0.x,e0.y,e0.z,e0.w, e1.x,e1.y,e1.z,e1.w,
                    o0.x,o0.y,o0.z,o0.w, o1.x,o1.y,o1.z,o1.w};
    ull acc[8];
    #pragma unroll
    for (int ko=0;ko<8;++ko) acc[ko]=0ull;
    #pragma unroll
    for (int j=0;j<16;++j){
        ull vj = pk2(xa[j], xa[j]);
        #pragma unroll
        for (int ko=0;ko<8;++ko) ffma2(acc[ko], vj, f[j*8+ko]);
    }
    float* ps = g_xs + soff + bt*CKD + c*8;
    float* pd = g_d + doff  + bt*CKD + c*8;
    float2 r0=up2(acc[0]), r1=up2(acc[1]), r2=up2(acc[2]), r3=up2(acc[3]);
    float2 r4=up2(acc[4]), r5=up2(acc[5]), r6=up2(acc[6]), r7=up2(acc[7]);
    *(float4*)ps     = make_float4(r0.x,r1.x,r2.x,r3.x);
    *(float4*)(ps+4) = make_float4(r4.x,r5.x,r6.x,r7.x);
    *(float4*)pd     = make_float4(r0.y,r1.y,r2.y,r3.y);
    *(float4*)(pd+4) = make_float4(r4.y,r5.y,r6.y,r7.y);
}

// ---------------- reconstruction ----------------
__global__ void __launch_bounds__(256) k_recon(long xoff, long uoff,
        float* __restrict__ oext, long ooff,
        const float* __restrict__ rce, const float* __restrict__ rco, int nh){
    __shared__ ull f[128];
    if (threadIdx.x < 128) f[threadIdx.x] = pk2(rce[threadIdx.x], rco[threadIdx.x]);
    __syncthreads();
    long idx = blockIdx.x*(long)blockDim.x + threadIdx.x;
    if (idx >= (long)16*nh*16) return;
    int c = (int)(idx & 15);
    long bt = idx >> 4;
    const float* px = g_xs + xoff + bt*CKD + c*8;
    const float* pu = g_us + uoff + bt*CKD + c*8;
    const float* pw = g_ud + uoff + bt*CKD + c*8;
    float4 a0 = *(const float4*)px,     u0 = *(const float4*)pu;
    float4 a1 = *(const float4*)(px+4), u1 = *(const float4*)(pu+4);
    float4 w0 = *(const float4*)pw,     w1 = *(const float4*)(pw+4);
    float xc[16] = {a0.x+u0.x, a0.y+u0.y, a0.z+u0.z, a0.w+u0.w,
                    a1.x+u1.x, a1.y+u1.y, a1.z+u1.z, a1.w+u1.w,
                    w0.x, w0.y, w0.z, w0.w, w1.x, w1.y, w1.z, w1.w};
    ull acc[8];
    #pragma unroll
    for (int ko=0;ko<8;++ko) acc[ko]=0ull;
    #pragma unroll
    for (int j=0;j<16;++j){
        ull vj = pk2(xc[j], xc[j]);
        #pragma unroll
        for (int ko=0;ko<8;++ko) ffma2(acc[ko], vj, f[j*8+ko]);
    }
    float* po = (oext ? oext : (g_xs + ooff)) + bt*2*CKD + c*8;
    float2 r0=up2(acc[0]), r1=up2(acc[1]), r2=up2(acc[2]), r3=up2(acc[3]);
    float2 r4=up2(acc[4]), r5=up2(acc[5]), r6=up2(acc[6]), r7=up2(acc[7]);
    *(float4*)po         = make_float4(r0.x,r1.x,r2.x,r3.x);
    *(float4*)(po+4)     = make_float4(r4.x,r5.x,r6.x,r7.x);
    *(float4*)(po+CKD)   = make_float4(r0.y,r1.y,r2.y,r3.y);
    *(float4*)(po+CKD+4) = make_float4(r4.y,r5.y,r6.y,r7.y);
}

// ---------------- folded forward DFT (shallow): 32 modes, 256 threads, L1-shared v loads ----------------
#define FDC(VR0, VR1, SL) { \
    float ax = VR0.x+VR1.x, ay = VR0.y+VR1.y; \
    float dx = VR0.x-VR1.x, dy = VR0.y-VR1.y; \
    ull a0 = pk2(ax,ax), a1 = pk2(ay,ay), d0 = pk2(dx,dx), d1 = pk2(dy,dy); \
    const ulonglong2* row_ = base + (SL)*4; \
    _Pragma("unroll") \
    for (int j_=0;j_<4;++j_){ \
        ulonglong2 t_ = row_[j_]; \
        ffma2(acc[j_*4+0], a0, t_.x); \
        ffma2(acc[j_*4+1], a1, t_.x); \
        ffma2(acc[j_*4+2], d0, t_.y); \
        ffma2(acc[j_*4+3], d1, t_.y); \
    } }

__global__ void __launch_bounds__(256) k_fdft(long voff, long twoff, int usepart,
        int n, int l){
    __shared__ ulonglong2 stw[1024];   // 4 h-groups x 64 s x 4 jj
    int tck = threadIdx.x & 63;
    int h   = threadIdx.x >> 6;        // 0..3
    int m0 = blockIdx.x * 32;
    int src = blockIdx.z >> 4;
    int b   = blockIdx.z & 15;
    int n2 = n >> 1;
    const float* vsrc = src ? (g_xs + voff) : g_d;
    float2* dstdir = src ? g_ftx : g_ftd;
    int ssp = gridDim.y;
    int chunk = n2 / ssp;
    int s0 = blockIdx.y * chunk;
    const float2* p2 = (const float2*)(vsrc + ((long)b*n + s0)*CKD) + tck;
    const float2* q2 = p2 + (long)n2*64;
    const ulonglong2* tw0 = g_ftw + twoff + ((long)blockIdx.x*4)*n2*4;
    ull acc[16];
    #pragma unroll
    for (int i=0;i<16;++i) acc[i]=0ull;

    for (int sb=0; sb<chunk; sb+=64){
        int tile = chunk - sb; if (tile > 64) tile = 64;
        for (int e = threadIdx.x; e < 1024; e += 256){
            int jj = e & 3, sl = (e >> 2) & 63, eh = e >> 8;   // eh 0..3
            ulonglong2 val = make_ulonglong2(0ull, 0ull);
            if (sl < tile)
                val = tw0[((long)eh*n2 + (s0+sb+sl))*4 + jj];
            stw[(eh*64 + sl)*4 + jj] = val;
        }
        __syncthreads();
        const ulonglong2* base = &stw[h*256];
        if ((tile & 7) == 0){
            int ng = tile >> 2;
            float2 r0[4], r1[4], u0[4], u1[4];
            #pragma unroll
            for (int i=0;i<4;++i){
                r0[i] = p2[(long)(sb+i)*64];
                r1[i] = q2[(long)(sb+i)*64];
            }
            for (int g=0; g<ng; g+=2){
                #pragma unroll
                for (int i=0;i<4;++i){
                    u0[i] = p2[(long)(sb+(g+1)*4+i)*64];
                    u1[i] = q2[(long)(sb+(g+1)*4+i)*64];
                }
                #pragma unroll
                for (int i=0;i<4;++i) FDC(r0[i], r1[i], g*4+i);
                if (g+2 < ng){
                    #pragma unroll
                    for (int i=0;i<4;++i){
                        r0[i] = p2[(long)(sb+(g+2)*4+i)*64];
                        r1[i] = q2[(long)(sb+(g+2)*4+i)*64];
                    }
                }
                #pragma unroll
                for (int i=0;i<4;++i) FDC(u0[i], u1[i], (g+1)*4+i);
            }
        } else {
            for (int sl=0; sl<tile; ++sl){
                float2 v0 = p2[(long)(sb+sl)*64];
                float2 v1 = q2[(long)(sb+sl)*64];
                FDC(v0, v1, sl);
            }
        }
        __syncthreads();
    }
    float2* dst = usepart
        ? (g_part + ((long)(src*ssp + blockIdx.y)*16 + b)*64*CKD)
        : (dstdir + (long)b*64*CKD);
    #pragma unroll
    for (int j=0;j<4;++j){
        int me = m0 + 8*h + 2*j;
        {
            float2 c0 = up2(acc[j*4+0]), c1 = up2(acc[j*4+1]);
            *(float4*)((float*)(dst + (long)me*CKD + 2*tck)) = make_float4(c0.x,c0.y,c1.x,c1.y);
        }
        {
            float2 c0 = up2(acc[j*4+2]), c1 = up2(acc[j*4+3]);
            *(float4*)((float*)(dst + (long)(me+1)*CKD + 2*tck)) = make_float4(c0.x,c0.y,c1.x,c1.y);
        }
    }
}

// ---------------- reduce s-split partials ----------------
__global__ void k_ftred(int l, int ssp){
    long idx = blockIdx.x*(long)blockDim.x + threadIdx.x;
    if (idx >= (long)16*l*CKD) return;
    int src = blockIdx.y;
    int ck = (int)(idx & 127);
    long r = idx >> 7;
    int m = (int)(r % l);
    int b = (int)(r / l);
    float2 a = make_float2(0.f, 0.f);
    for (int sp=0; sp<ssp; ++sp){
        float2 p = g_part[((long)(src*ssp + sp)*16 + b)*64*CKD + (long)m*CKD + ck];
        a.x += p.x; a.y += p.y;
    }
    (src ? g_ftx : g_ftd)[((long)b*64 + m)*CKD + ck] = a;
}

// ---------------- merged mode mixing (shallow): 8 batches/block, grid (lm, 2) ----------------
__global__ void __launch_bounds__(128) k_mix(int l){
    __shared__ __align__(16) ull sda[128*8], sdb[128*8], sxa[128*8], sxb[128*8];
    int o = threadIdx.x;
    int m = blockIdx.x;
    int bg = blockIdx.y;
    const float2* ftd = g_ftd + (long)bg*8*64*CKD;
    const float2* ftx = g_ftx + (long)bg*8*64*CKD;
    float2* oud = g_oud + (long)bg*8*64*CKD;
    float2* ous = g_ous + (long)bg*8*64*CKD;
    #pragma unroll
    for (int j=0;j<8;++j){
        float2 f = ftd[(long)j*64*CKD + (long)m*CKD + o];
        sda[o*8+j] = pk2(f.x, f.x);
        sdb[o*8+j] = pk2(-f.y, f.y);
        float2 g = ftx[(long)j*64*CKD + (long)m*CKD + o];
        sxa[o*8+j] = pk2(g.x, g.x);
        sxb[o*8+j] = pk2(-g.y, g.y);
    }
    __syncthreads();
    const float2* wA = g_wt + (long)m*16384 + o;
    const float2* wB = wA + (long)64*16384;
    const float2* wC = wB + (long)64*16384;
    ull ud[8], us[8];
    #pragma unroll
    for (int j=0;j<8;++j){ ud[j]=0ull; us[j]=0ull; }
    #pragma unroll 2
    for (int i=0;i<128;++i){
        float2 a = wA[(long)i*CKD];
        float2 b = wB[(long)i*CKD];
        float2 c = wC[(long)i*CKD];
        ull Ap = pk2(a.x, a.y), As = pk2(a.y, a.x);
        ull Bp = pk2(b.x, b.y), Bs = pk2(b.y, b.x);
        ull Cp = pk2(c.x, c.y), Cs = pk2(c.y, c.x);
        #pragma unroll
        for (int k=0;k<4;++k){
            ulonglong2 d2 = *(const ulonglong2*)&sda[i*8 + 2*k];
            ulonglong2 e2 = *(const ulonglong2*)&sdb[i*8 + 2*k];
            ulonglong2 x2 = *(const ulonglong2*)&sxa[i*8 + 2*k];
            ulonglong2 y2 = *(const ulonglong2*)&sxb[i*8 + 2*k];
            ffma2(ud[2*k],   d2.x, Ap); ffma2(ud[2*k],   e2.x, As);
            ffma2(ud[2*k],   x2.x, Bp); ffma2(ud[2*k],   y2.x, Bs);
            ffma2(us[2*k],   d2.x, Cp); ffma2(us[2*k],   e2.x, Cs);
            ffma2(ud[2*k+1], d2.y, Ap); ffma2(ud[2*k+1], e2.y, As);
            ffma2(ud[2*k+1], x2.y, Bp); ffma2(ud[2*k+1], y2.y, Bs);
            ffma2(us[2*k+1], d2.y, Cp); ffma2(us[2*k+1], e2.y, Cs);
        }
    }
    #pragma unroll
    for (int j=0;j<8;++j){
        oud[(long)j*64*CKD + (long)m*CKD + o] = up2(ud[j]);
        ous[(long)j*64*CKD + (long)m*CKD + o] = up2(us[j]);
    }
}

// ---------------- folded inverse DFT (shallow): precomputed tables, parity split ----------------
__global__ void __launch_bounds__(256) k_idft(long uoff, long twoff, int n, int l){
    __shared__ ulonglong2 tab[64*16];
    __shared__ ull stash[16*128];
    int tck = threadIdx.x & 63;
    int parity = (threadIdx.x >> 6) & 1;
    int sub = threadIdx.x >> 7;
    int b  = blockIdx.y;
    int n2 = n >> 1;
    int tb = blockIdx.x * 16;
    const ulonglong2* itw = g_ftw + twoff;
    for (int q = threadIdx.x; q < l*16; q += 256){
        int m = q >> 4, tp = q & 15;
        int t = tb + tp;
        ulonglong2 val = make_ulonglong2(0ull, 0ull);
        if (t < n2) val = itw[(long)m*n2 + t];
        tab[q] = val;
    }
    __syncthreads();
    const float4* pod4 = (const float4*)(g_oud + (long)b*64*CKD) + tck;
    const float4* pos4 = (const float4*)(g_ous + (long)b*64*CKD) + tck;
    ull acc[16];
    #pragma unroll
    for (int i=0;i<16;++i) acc[i]=0ull;
    int mcount = (l - parity + 1) >> 1;
    if (mcount > 0){
        float4 yd = pod4[(long)parity*64];
        float4 ys = pos4[(long)parity*64];
        for (int k=0; k<mcount; ++k){
            int m = parity + 2*k;
            float4 ydn = make_float4(0,0,0,0), ysn = make_float4(0,0,0,0);
            if (k+1 < mcount){
                ydn = pod4[(long)(m+2)*64];
                ysn = pos4[(long)(m+2)*64];
            }
            ull re0 = pk2(yd.x, ys.x), im0 = pk2(yd.y, ys.y);
            ull re1 = pk2(yd.z, ys.z), im1 = pk2(yd.w, ys.w);
            const ulonglong2* row = &tab[m*16 + sub*8];
            #pragma unroll
            for (int tp=0; tp<8; ++tp){
                ulonglong2 t2 = row[tp];
                ffma2(acc[tp*2],   re0, t2.x);
                ffma2(acc[tp*2],   im0, t2.y);
                ffma2(acc[tp*2+1], re1, t2.x);
                ffma2(acc[tp*2+1], im1, t2.y);
            }
            yd = ydn; ys = ysn;
        }
    }
    if (parity == 0){
        #pragma unroll
        for (int i=0;i<16;++i) stash[i*128 + sub*64 + tck] = acc[i];
    }
    __syncthreads();
    if (parity == 1){
        float* pud = g_ud + uoff + (long)b*n*CKD + 2*tck;
        float* pus = g_us + uoff + (long)b*n*CKD + 2*tck;
        #pragma unroll
        for (int tp=0; tp<8; ++tp){
            int t = tb + sub*8 + tp;
            if (t < n2){
                float2 E0 = up2(stash[(tp*2)*128   + sub*64 + tck]);
                float2 E1 = up2(stash[(tp*2+1)*128 + sub*64 + tck]);
                float2 O0 = up2(acc[tp*2]), O1 = up2(acc[tp*2+1]);
                *(float2*)(pud + (long)t*CKD)      = make_float2(E0.x+O0.x, E1.x+O1.x);
                *(float2*)(pus + (long)t*CKD)      = make_float2(E0.y+O0.y, E1.y+O1.y);
                *(float2*)(pud + (long)(t+n2)*CKD) = make_float2(E0.x-O0.x, E1.x-O1.x);
                *(float2*)(pus + (long)(t+n2)*CKD) = make_float2(E0.y-O0.y, E1.y-O1.y);
            }
        }
    }
}

// ---------------- batched deep kernels (unchanged from R12/R13) ----------------
__device__ const long DOFFd[7] = {0,131072,196608,229376,245760,253952,258048};

__global__ void __launch_bounds__(128) k_dfdft(){
    __shared__ float vb[64*128];
    int li = blockIdx.x, b = blockIdx.y, src = blockIdx.z;
    int nh = 64 >> li, n2 = nh >> 1, lm = n2 + 1;
    int stride = 64 << li;
    int ck = threadIdx.x;
    long soff = off_level(6+li);
    const float* v = src ? (g_xs + soff + (long)b*nh*CKD)
                         : (g_d + DOFFd[li] + (long)b*nh*CKD);
    float2* dst = g_part + DEEP_FT_BASE + ((long)(li*16+b)*2 + src)*64*CKD;
    if (n2 == 0){
        dst[ck] = make_float2(v[ck], 0.f);
        return;
    }
    for (int i = ck; i < nh*CKD; i += 128) vb[i] = v[i];
    __syncthreads();
    for (int m = 0; m < lm; ++m){
        float ar = 0.f, ai = 0.f;
        for (int s = 0; s < n2; ++s){
            float v0 = vb[s*CKD + ck], v1 = vb[(s+n2)*CKD + ck];
            float a = (m & 1) ? (v0 - v1) : (v0 + v1);
            float2 t = g_tw[(m*s*stride) & 4095];
            ar = fmaf(a, t.x, ar);
            ai = fmaf(a, t.y, ai);
        }
        dst[(long)m*CKD + ck] = make_float2(ar, ai);
    }
}

__global__ void __launch_bounds__(128) k_dmix(){
    __shared__ __align__(16) ull sda[128*4], sdb[128*4], sxa[128*4], sxb[128*4];
    int g = blockIdx.x;
    int li, m;
    if (g < 33){ li=0; m=g; }
    else if (g < 50){ li=1; m=g-33; }
    else if (g < 59){ li=2; m=g-50; }
    else if (g < 64){ li=3; m=g-59; }
    else if (g < 67){ li=4; m=g-64; }
    else if (g < 69){ li=5; m=g-67; }
    else { li=6; m=g-69; }
    int bg = blockIdx.y;
    int o = threadIdx.x;
    const float2* ftd = g_part + DEEP_FT_BASE + ((long)(li*16 + bg*4)*2 + 0)*64*CKD;
    const float2* ftx = g_part + DEEP_FT_BASE + ((long)(li*16 + bg*4)*2 + 1)*64*CKD;
    float2* oud = g_part + DEEP_OU_BASE + ((long)(li*16 + bg*4)*2 + 0)*64*CKD;
    float2* ous = g_part + DEEP_OU_BASE + ((long)(li*16 + bg*4)*2 + 1)*64*CKD;
    #pragma unroll
    for (int j=0;j<4;++j){
        float2 f = ftd[(long)j*2*64*CKD + (long)m*CKD + o];
        sda[o*4+j] = pk2(f.x, f.x);
        sdb[o*4+j] = pk2(-f.y, f.y);
        float2 gg = ftx[(long)j*2*64*CKD + (long)m*CKD + o];
        sxa[o*4+j] = pk2(gg.x, gg.x);
        sxb[o*4+j] = pk2(-gg.y, gg.y);
    }
    __syncthreads();
    const float2* wA = g_wt + (long)m*16384 + o;
    const float2* wB = wA + (long)64*16384;
    const float2* wC = wB + (long)64*16384;
    ull ud[4], us[4];
    #pragma unroll
    for (int j=0;j<4;++j){ ud[j]=0ull; us[j]=0ull; }
    #pragma unroll 2
    for (int i=0;i<128;++i){
        float2 a = wA[(long)i*CKD];
        float2 b = wB[(long)i*CKD];
        float2 c = wC[(long)i*CKD];
        ull Ap = pk2(a.x, a.y), As = pk2(a.y, a.x);
        ull Bp = pk2(b.x, b.y), Bs = pk2(b.y, b.x);
        ull Cp = pk2(c.x, c.y), Cs = pk2(c.y, c.x);
        ulonglong2 d01 = *(const ulonglong2*)&sda[i*4];
        ulonglong2 d23 = *(const ulonglong2*)&sda[i*4+2];
        ulonglong2 e01 = *(const ulonglong2*)&sdb[i*4];
        ulonglong2 e23 = *(const ulonglong2*)&sdb[i*4+2];
        ulonglong2 x01 = *(const ulonglong2*)&sxa[i*4];
        ulonglong2 x23 = *(const ulonglong2*)&sxa[i*4+2];
        ulonglong2 y01 = *(const ulonglong2*)&sxb[i*4];
        ulonglong2 y23 = *(const ulonglong2*)&sxb[i*4+2];
        ffma2(ud[0], d01.x, Ap); ffma2(ud[0], e01.x, As);
        ffma2(ud[0], x01.x, Bp); ffma2(ud[0], y01.x, Bs);
        ffma2(us[0], d01.x, Cp); ffma2(us[0], e01.x, Cs);
        ffma2(ud[1], d01.y, Ap); ffma2(ud[1], e01.y, As);
        ffma2(ud[1], x01.y, Bp); ffma2(ud[1], y01.y, Bs);
        ffma2(us[1], d01.y, Cp); ffma2(us[1], e01.y, Cs);
        ffma2(ud[2], d23.x, Ap); ffma2(ud[2], e23.x, As);
        ffma2(ud[2], x23.x, Bp); ffma2(ud[2], y23.x, Bs);
        ffma2(us[2], d23.x, Cp); ffma2(us[2], e23.x, Cs);
        ffma2(ud[3], d23.y, Ap); ffma2(ud[3], e23.y, As);
        ffma2(ud[3], x23.y, Bp); ffma2(ud[3], y23.y, Bs);
        ffma2(us[3], d23.y, Cp); ffma2(us[3], e23.y, Cs);
    }
    #pragma unroll
    for (int j=0;j<4;++j){
        oud[(long)j*2*64*CKD + (long)m*CKD + o] = up2(ud[j]);
        ous[(long)j*2*64*CKD + (long)m*CKD + o] = up2(us[j]);
    }
}

__global__ void __launch_bounds__(128) k_didft(){
    int xb = blockIdx.x;
    int li = (xb < 2) ? 0 : xb - 1;
    int tb = (xb == 1) ? 16 : 0;
    int b = blockIdx.y;
    int nh = 64 >> li, n2 = nh >> 1, lm = n2 + 1;
    int stride = 64 << li;
    float invn = 1.0f / (float)nh;
    int ck = threadIdx.x;
    long soff = off_level(6+li);
    const float2* oud = g_part + DEEP_OU_BASE + ((long)(li*16+b)*2 + 0)*64*CKD;
    const float2* ous = g_part + DEEP_OU_BASE + ((long)(li*16+b)*2 + 1)*64*CKD;
    float* pud = g_ud + soff + (long)b*nh*CKD;
    float* pus = g_us + soff + (long)b*nh*CKD;
    if (n2 == 0){
        pud[ck] = oud[ck].x;
        pus[ck] = ous[ck].x;
        return;
    }
    int tcount = n2 - tb; if (tcount > 16) tcount = 16;
    if (tcount <= 0) return;
    for (int tp = 0; tp < tcount; ++tp){
        int t = tb + tp;
        float eu=0.f, ou=0.f, es=0.f, os=0.f;
        for (int m = 0; m < lm; ++m){
            float2 y = oud[(long)m*CKD + ck];
            float2 z = ous[(long)m*CKD + ck];
            float2 e = g_tw[(m*t*stride) & 4095];
            float sc = ((m==0) || (2*m==nh)) ? invn : 2.f*invn;
            float vu = sc*(y.x*e.x + y.y*e.y);
            float vs = sc*(z.x*e.x + z.y*e.y);
            if (m & 1){ ou += vu; os += vs; } else { eu += vu; es += vs; }
        }
        pud[(long)t*CKD + ck]      = eu + ou;
        pus[(long)t*CKD + ck]      = es + os;
        pud[(long)(t+n2)*CKD + ck] = eu - ou;
        pus[(long)(t+n2)*CKD + ck] = es - os;
    }
}

// ---------------- LayerNorm + exact GELU ----------------
__global__ void k_lngelu(const float* __restrict__ w, const float* __restrict__ bia, long off){
    int b = blockIdx.x, t = threadIdx.x;
    __shared__ float rs[8];
    float v = g_xs[off + (long)b*CKD + t];
    float s1 = v, s2 = v*v;
    #pragma unroll
    for (int o=16; o; o>>=1){
        s1 += __shfl_xor_sync(0xffffffffu, s1, o);
        s2 += __shfl_xor_sync(0xffffffffu, s2, o);
    }
    if ((t & 31) == 0){ rs[t>>5] = s1; rs[4+(t>>5)] = s2; }
    __syncthreads();
    float m1 = (rs[0]+rs[1]+rs[2]+rs[3]) * (1.0f/128.0f);
    float m2 = (rs[4]+rs[5]+rs[6]+rs[7]) * (1.0f/128.0f);
    float var = m2 - m1*m1;
    float xn = (v - m1) * rsqrtf(var + 1e-5f) * w[t] + bia[t];
    float ge = 0.5f * xn * (1.0f + erff(xn * 0.70710678118654752f));
    g_xs[off + (long)b*CKD + t] = ge;
}

// ---------------- host ----------------
extern "C" void kernel_launch(void* const* d_in, const int* in_sizes, int n_in,
                              void* d_out, int out_size) {
    const float* x   = (const float*)d_in[0];
    const float* Awr = (const float*)d_in[1];
    const float* Awi = (const float*)d_in[2];
    const float* Bwr = (const float*)d_in[3];
    const float* Bwi = (const float*)d_in[4];
    const float* Cwr = (const float*)d_in[5];
    const float* Cwi = (const float*)d_in[6];
    const float* lnw = (const float*)d_in[7];
    const float* lnb = (const float*)d_in[8];
    const float* ecs = (const float*)d_in[9];
    const float* ecd = (const float*)d_in[10];
    const float* rce = (const float*)d_in[11];
    const float* rco = (const float*)d_in[12];
    float* out = (float*)d_out;

    static const int NH[13]  = {4096,2048,1024,512,256,128,64,32,16,8,4,2,1};
    static const int LM[13]  = {64,64,64,64,64,64,33,17,9,5,3,2,1};
    static const int SSP[6]  = {16,16,8,4,2,1};
    static const long DOFFh[7] = {0,131072,196608,229376,245760,253952,258048};
    static const long TWOFF[6] = {0, 196608, 294912, 344064, 368640, 380928};
    long OFF[13];
    OFF[0] = 0;
    for (int l=1; l<13; ++l) OFF[l] = OFF[l-1] + (long)16*NH[l-1]*128;

    k_base<<<16, 256>>>();
    k_tw_all<<<(387072+255)/256, 256>>>();
    long wthr = (long)3*64*128*128;
    k_wtrans<<<(unsigned)((wthr+255)/256), 256>>>(Awr, Awi, Bwr, Bwi, Cwr, Cwi);

    // shallow levels 0..5
    for (int l=0; l<6; ++l){
        int nh = NH[l], lm = LM[l], ssp = SSP[l];
        int n2 = nh >> 1;
        long nthr = (long)16*nh*16;
        unsigned blk = (unsigned)((nthr + 255) / 256);
        k_decompose<<<blk, 256>>>(l==0 ? x : (const float*)0, l ? OFF[l-1] : 0,
                                  OFF[l], 0L, ecs, ecd, nh);
        dim3 gf((lm+31)/32, ssp, 32);
        k_fdft<<<gf, 256>>>(OFF[l], TWOFF[l], ssp>1 ? 1 : 0, nh, lm);
        if (ssp > 1){
            unsigned rb = (unsigned)(((long)16*lm*128 + 255)/256);
            k_ftred<<<dim3(rb, 2), 256>>>(lm, ssp);
        }
        k_mix<<<dim3(lm, 2), 128>>>(lm);
        int gx = (n2 + 15)/16;
        k_idft<<<dim3(gx, 16), 256>>>(OFF[l], TWOFF[l] + (long)32*n2, nh, lm);
    }

    // deep decompose chain (levels 6..12)
    for (int l=6; l<13; ++l){
        int nh = NH[l];
        long nthr = (long)16*nh*16;
        unsigned blk = (unsigned)((nthr + 255) / 256);
        k_decompose<<<blk, 256>>>((const float*)0, OFF[l-1], OFF[l], DOFFh[l-6],
                                  ecs, ecd, nh);
    }
    // batched deep spectral path
    k_dfdft<<<dim3(7,16,2), 128>>>();
    k_dmix<<<dim3(70,4), 128>>>();
    k_didft<<<dim3(8,16), 128>>>();

    k_lngelu<<<16, 128>>>(lnw, lnb, OFF[12]);

    // deep recon chain 12..6
    for (int l=12; l>=6; --l){
        int nh = NH[l];
        long nthr = (long)16*nh*16;
        unsigned blk = (unsigned)((nthr + 255) / 256);
        k_recon<<<blk, 256>>>(OFF[l], OFF[l], (float*)0, OFF[l-1], rce, rco, nh);
    }
    // shallow recon 5..0
    for (int l=5; l>=0; --l){
        int nh = NH[l];
        long nthr = (long)16*nh*16;
        unsigned blk = (unsigned)((nthr + 255) / 256);
        k_recon<<<blk, 256>>>(OFF[l], OFF[l],
                              l ? (float*)0 : out, l ? OFF[l-1] : 0,
                              rce, rco, nh);
    }
}

// round 15
// speedup vs baseline: 1.0479x; 1.0479x over previous
#include <cuda_runtime.h>
#include <cuda_bf16.h>

#define CKD 128
typedef unsigned long long ull;

// ---------------- static scratch ----------------
__device__ float  g_xs[(long)16*8191*128];
__device__ float  g_d [(long)16*4096*128];
__device__ float  g_ud[(long)16*8191*128];
__device__ float  g_us[(long)16*8191*128];
__device__ float2 g_part[(long)2*16*16*64*128];
__device__ float2 g_ftd[16*64*128];
__device__ float2 g_ftx[16*64*128];
__device__ float2 g_oud[16*64*128];
__device__ float2 g_ous[16*64*128];
__device__ float2 g_wt[(long)3*64*128*128];
__device__ float2 g_tw[4096+64];
__device__ ulonglong2 g_ftw[(long)96*4096];

#define DEEP_FT_BASE 0L
#define DEEP_OU_BASE 1835008L

// ---------------- f32x2 helpers ----------------
__device__ __forceinline__ ull pk2(float x, float y){
    ull r; asm("mov.b64 %0, {%1, %2};" : "=l"(r) : "f"(x), "f"(y)); return r;
}
__device__ __forceinline__ float2 up2(ull v){
    float2 r; asm("mov.b64 {%0, %1}, %2;" : "=f"(r.x), "=f"(r.y) : "l"(v)); return r;
}
__device__ __forceinline__ void ffma2(ull &acc, ull a, ull b){
    asm("fma.rn.f32x2 %0, %1, %2, %0;" : "+l"(acc) : "l"(a), "l"(b));
}
__device__ __forceinline__ long off_level(int l){
    long o = 0; int nhf = 4096;
    for (int i=0;i<l;++i){ o += (long)16*nhf*128; nhf >>= 1; }
    return o;
}
__device__ __forceinline__ float2 twid(int r){
    float sn, cs;
    sincospif((float)r * (-1.0f/2048.0f), &sn, &cs);
    return make_float2(cs, sn);
}

// ---------------- base twiddle table (deep kernels) ----------------
__global__ void k_base(){
    int r = blockIdx.x*blockDim.x + threadIdx.x;
    if (r >= 4096) return;
    float s, c;
    sincospif(r/2048.0f, &s, &c);
    g_tw[r] = make_float2(c, -s);
    if (r < 64) g_tw[4096+r] = make_float2(0.f, 0.f);
}

// ---------------- batched packed twiddle tables for shallow levels 0..5 ----------------
__global__ void k_tw_all(){
    const int CUM[7] = {0, 196608, 294912, 344064, 368640, 380928, 387072};
    int idx = blockIdx.x*blockDim.x + threadIdx.x;
    if (idx >= 387072) return;
    int l = 0;
    #pragma unroll
    for (int i=1; i<6; ++i) if (idx >= CUM[i]) l = i;
    int local = idx - CUM[l];
    int n2 = 2048 >> l;
    int stride = 1 << l;
    int n = 4096 >> l;
    float invn = 1.0f / (float)n;
    long base = CUM[l];
    long nf = (long)32*n2;
    if (local < nf){
        int jj = local & 3;
        int r = local >> 2;
        int s = r % n2;
        int gh = r / n2;
        int me = (gh>>1)*16 + (gh&1)*8 + 2*jj;
        int mo = me + 1;
        float2 te = twid((me*s*stride)&4095);
        float2 to = twid((mo*s*stride)&4095);
        g_ftw[base + local] = make_ulonglong2(pk2(te.x,te.y), pk2(to.x,to.y));
    } else {
        int r = local - (int)nf;
        int m = r / n2;
        int t = r - m*n2;
        float2 e = twid((m*t*stride)&4095);
        float sc = (m==0) ? invn : 2.f*invn;
        g_ftw[base + local] = make_ulonglong2(pk2(sc*e.x, sc*e.x), pk2(sc*e.y, sc*e.y));
    }
}

// ---------------- weight transpose ----------------
__global__ void k_wtrans(const float* __restrict__ Ar, const float* __restrict__ Ai,
                         const float* __restrict__ Br, const float* __restrict__ Bi,
                         const float* __restrict__ Cr, const float* __restrict__ Ci){
    long gidx = blockIdx.x*(long)blockDim.x + threadIdx.x;
    const long per = (long)64*128*128;
    if (gidx >= 3*per) return;
    int mat = (int)(gidx / per);
    long idx = gidx - (long)mat*per;
    const float* wr = mat==0 ? Ar : (mat==1 ? Br : Cr);
    const float* wi = mat==0 ? Ai : (mat==1 ? Bi : Ci);
    int m = (int)(idx & 63);
    int o = (int)((idx >> 6) & 127);
    int i = (int)(idx >> 13);
    g_wt[((long)mat*64 + m)*16384 + (long)i*128 + o] = make_float2(wr[idx], wi[idx]);
}

// ---------------- wavelet decompose ----------------
__global__ void __launch_bounds__(256) k_decompose(const float* __restrict__ xext, long xoff,
        long soff, long doff,
        const float* __restrict__ ecs, const float* __restrict__ ecd, int nh){
    __shared__ ull f[128];
    if (threadIdx.x < 128) f[threadIdx.x] = pk2(ecs[threadIdx.x], ecd[threadIdx.x]);
    __syncthreads();
    long idx = blockIdx.x*(long)blockDim.x + threadIdx.x;
    if (idx >= (long)16*nh*16) return;
    int c = (int)(idx & 15);
    long bt = idx >> 4;
    const float* xin = xext ? xext : (g_xs + xoff);
    const float* pe = xin + bt*2*CKD + c*8;
    float4 e0 = *(const float4*)(pe);
    float4 e1 = *(const float4*)(pe+4);
    float4 o0 = *(const float4*)(pe+CKD);
    float4 o1 = *(const float4*)(pe+CKD+4);
    float xa[16] = {e0.x,e0.y,e0.z,e0.w, e1.x,e1.y,e1.z,e1.w,
                    o0.x,o0.y,o0.z,o0.w, o1.x,o1.y,o1.z,o1.w};
    ull acc[8];
    #pragma unroll
    for (int ko=0;ko<8;++ko) acc[ko]=0ull;
    #pragma unroll
    for (int j=0;j<16;++j){
        ull vj = pk2(xa[j], xa[j]);
        #pragma unroll
        for (int ko=0;ko<8;++ko) ffma2(acc[ko], vj, f[j*8+ko]);
    }
    float* ps = g_xs + soff + bt*CKD + c*8;
    float* pd = g_d + doff  + bt*CKD + c*8;
    float2 r0=up2(acc[0]), r1=up2(acc[1]), r2=up2(acc[2]), r3=up2(acc[3]);
    float2 r4=up2(acc[4]), r5=up2(acc[5]), r6=up2(acc[6]), r7=up2(acc[7]);
    *(float4*)ps     = make_float4(r0.x,r1.x,r2.x,r3.x);
    *(float4*)(ps+4) = make_float4(r4.x,r5.x,r6.x,r7.x);
    *(float4*)pd     = make_float4(r0.y,r1.y,r2.y,r3.y);
    *(float4*)(pd+4) = make_float4(r4.y,r5.y,r6.y,r7.y);
}

// ---------------- reconstruction ----------------
__global__ void __launch_bounds__(256) k_recon(long xoff, long uoff,
        float* __restrict__ oext, long ooff,
        const float* __restrict__ rce, const float* __restrict__ rco, int nh){
    __shared__ ull f[128];
    if (threadIdx.x < 128) f[threadIdx.x] = pk2(rce[threadIdx.x], rco[threadIdx.x]);
    __syncthreads();
    long idx = blockIdx.x*(long)blockDim.x + threadIdx.x;
    if (idx >= (long)16*nh*16) return;
    int c = (int)(idx & 15);
    long bt = idx >> 4;
    const float* px = g_xs + xoff + bt*CKD + c*8;
    const float* pu = g_us + uoff + bt*CKD + c*8;
    const float* pw = g_ud + uoff + bt*CKD + c*8;
    float4 a0 = *(const float4*)px,     u0 = *(const float4*)pu;
    float4 a1 = *(const float4*)(px+4), u1 = *(const float4*)(pu+4);
    float4 w0 = *(const float4*)pw,     w1 = *(const float4*)(pw+4);
    float xc[16] = {a0.x+u0.x, a0.y+u0.y, a0.z+u0.z, a0.w+u0.w,
                    a1.x+u1.x, a1.y+u1.y, a1.z+u1.z, a1.w+u1.w,
                    w0.x, w0.y, w0.z, w0.w, w1.x, w1.y, w1.z, w1.w};
    ull acc[8];
    #pragma unroll
    for (int ko=0;ko<8;++ko) acc[ko]=0ull;
    #pragma unroll
    for (int j=0;j<16;++j){
        ull vj = pk2(xc[j], xc[j]);
        #pragma unroll
        for (int ko=0;ko<8;++ko) ffma2(acc[ko], vj, f[j*8+ko]);
    }
    float* po = (oext ? oext : (g_xs + ooff)) + bt*2*CKD + c*8;
    float2 r0=up2(acc[0]), r1=up2(acc[1]), r2=up2(acc[2]), r3=up2(acc[3]);
    float2 r4=up2(acc[4]), r5=up2(acc[5]), r6=up2(acc[6]), r7=up2(acc[7]);
    *(float4*)po         = make_float4(r0.x,r1.x,r2.x,r3.x);
    *(float4*)(po+4)     = make_float4(r4.x,r5.x,r6.x,r7.x);
    *(float4*)(po+CKD)   = make_float4(r0.y,r1.y,r2.y,r3.y);
    *(float4*)(po+CKD+4) = make_float4(r4.y,r5.y,r6.y,r7.y);
}

// ---------------- folded forward DFT (shallow): R13 config (16 modes, 128 thr) ----------------
#define FDC(VR0, VR1, SL) { \
    float ax = VR0.x+VR1.x, ay = VR0.y+VR1.y; \
    float dx = VR0.x-VR1.x, dy = VR0.y-VR1.y; \
    ull a0 = pk2(ax,ax), a1 = pk2(ay,ay), d0 = pk2(dx,dx), d1 = pk2(dy,dy); \
    const ulonglong2* row_ = base + (SL)*4; \
    _Pragma("unroll") \
    for (int j_=0;j_<4;++j_){ \
        ulonglong2 t_ = row_[j_]; \
        ffma2(acc[j_*4+0], a0, t_.x); \
        ffma2(acc[j_*4+1], a1, t_.x); \
        ffma2(acc[j_*4+2], d0, t_.y); \
        ffma2(acc[j_*4+3], d1, t_.y); \
    } }

__global__ void __launch_bounds__(128) k_fdft(long voff, long twoff, int usepart,
        int n, int l){
    __shared__ ulonglong2 stw[512];
    int tck = threadIdx.x & 63;
    int h   = threadIdx.x >> 6;
    int m0 = blockIdx.x * 16;
    int src = blockIdx.z >> 4;
    int b   = blockIdx.z & 15;
    int n2 = n >> 1;
    const float* vsrc = src ? (g_xs + voff) : g_d;
    float2* dstdir = src ? g_ftx : g_ftd;
    int ssp = gridDim.y;
    int chunk = n2 / ssp;
    int s0 = blockIdx.y * chunk;
    const float2* p2 = (const float2*)(vsrc + ((long)b*n + s0)*CKD) + tck;
    const float2* q2 = p2 + (long)n2*64;
    const ulonglong2* tw0 = g_ftw + twoff + ((long)blockIdx.x*2)*n2*4;
    ull acc[16];
    #pragma unroll
    for (int i=0;i<16;++i) acc[i]=0ull;

    for (int sb=0; sb<chunk; sb+=64){
        int tile = chunk - sb; if (tile > 64) tile = 64;
        for (int e = threadIdx.x; e < 512; e += 128){
            int jj = e & 3, sl = (e >> 2) & 63, eh = e >> 8;
            ulonglong2 val = make_ulonglong2(0ull, 0ull);
            if (sl < tile)
                val = tw0[((long)eh*n2 + (s0+sb+sl))*4 + jj];
            stw[(eh*64 + sl)*4 + jj] = val;
        }
        __syncthreads();
        const ulonglong2* base = &stw[h*256];
        if ((tile & 7) == 0){
            int ng = tile >> 2;
            float2 r0[4], r1[4], u0[4], u1[4];
            #pragma unroll
            for (int i=0;i<4;++i){
                r0[i] = p2[(long)(sb+i)*64];
                r1[i] = q2[(long)(sb+i)*64];
            }
            for (int g=0; g<ng; g+=2){
                #pragma unroll
                for (int i=0;i<4;++i){
                    u0[i] = p2[(long)(sb+(g+1)*4+i)*64];
                    u1[i] = q2[(long)(sb+(g+1)*4+i)*64];
                }
                #pragma unroll
                for (int i=0;i<4;++i) FDC(r0[i], r1[i], g*4+i);
                if (g+2 < ng){
                    #pragma unroll
                    for (int i=0;i<4;++i){
                        r0[i] = p2[(long)(sb+(g+2)*4+i)*64];
                        r1[i] = q2[(long)(sb+(g+2)*4+i)*64];
                    }
                }
                #pragma unroll
                for (int i=0;i<4;++i) FDC(u0[i], u1[i], (g+1)*4+i);
            }
        } else {
            for (int sl=0; sl<tile; ++sl){
                float2 v0 = p2[(long)(sb+sl)*64];
                float2 v1 = q2[(long)(sb+sl)*64];
                FDC(v0, v1, sl);
            }
        }
        __syncthreads();
    }
    float2* dst = usepart
        ? (g_part + ((long)(src*ssp + blockIdx.y)*16 + b)*64*CKD)
        : (dstdir + (long)b*64*CKD);
    #pragma unroll
    for (int j=0;j<4;++j){
        int me = m0 + 8*h + 2*j;
        {
            float2 c0 = up2(acc[j*4+0]), c1 = up2(acc[j*4+1]);
            *(float4*)((float*)(dst + (long)me*CKD + 2*tck)) = make_float4(c0.x,c0.y,c1.x,c1.y);
        }
        {
            float2 c0 = up2(acc[j*4+2]), c1 = up2(acc[j*4+3]);
            *(float4*)((float*)(dst + (long)(me+1)*CKD + 2*tck)) = make_float4(c0.x,c0.y,c1.x,c1.y);
        }
    }
}

// ---------------- reduce s-split partials ----------------
__global__ void k_ftred(int l, int ssp){
    long idx = blockIdx.x*(long)blockDim.x + threadIdx.x;
    if (idx >= (long)16*l*CKD) return;
    int src = blockIdx.y;
    int ck = (int)(idx & 127);
    long r = idx >> 7;
    int m = (int)(r % l);
    int b = (int)(r / l);
    float2 a = make_float2(0.f, 0.f);
    for (int sp=0; sp<ssp; ++sp){
        float2 p = g_part[((long)(src*ssp + sp)*16 + b)*64*CKD + (long)m*CKD + ck];
        a.x += p.x; a.y += p.y;
    }
    (src ? g_ftx : g_ftd)[((long)b*64 + m)*CKD + ck] = a;
}

// ---------------- merged mode mixing (shallow): 8 batches/block, grid (lm, 2) ----------------
__global__ void __launch_bounds__(128) k_mix(int l){
    __shared__ __align__(16) ull sda[128*8], sdb[128*8], sxa[128*8], sxb[128*8];
    int o = threadIdx.x;
    int m = blockIdx.x;
    int bg = blockIdx.y;
    const float2* ftd = g_ftd + (long)bg*8*64*CKD;
    const float2* ftx = g_ftx + (long)bg*8*64*CKD;
    float2* oud = g_oud + (long)bg*8*64*CKD;
    float2* ous = g_ous + (long)bg*8*64*CKD;
    #pragma unroll
    for (int j=0;j<8;++j){
        float2 f = ftd[(long)j*64*CKD + (long)m*CKD + o];
        sda[o*8+j] = pk2(f.x, f.x);
        sdb[o*8+j] = pk2(-f.y, f.y);
        float2 g = ftx[(long)j*64*CKD + (long)m*CKD + o];
        sxa[o*8+j] = pk2(g.x, g.x);
        sxb[o*8+j] = pk2(-g.y, g.y);
    }
    __syncthreads();
    const float2* wA = g_wt + (long)m*16384 + o;
    const float2* wB = wA + (long)64*16384;
    const float2* wC = wB + (long)64*16384;
    ull ud[8], us[8];
    #pragma unroll
    for (int j=0;j<8;++j){ ud[j]=0ull; us[j]=0ull; }
    #pragma unroll 2
    for (int i=0;i<128;++i){
        float2 a = wA[(long)i*CKD];
        float2 b = wB[(long)i*CKD];
        float2 c = wC[(long)i*CKD];
        ull Ap = pk2(a.x, a.y), As = pk2(a.y, a.x);
        ull Bp = pk2(b.x, b.y), Bs = pk2(b.y, b.x);
        ull Cp = pk2(c.x, c.y), Cs = pk2(c.y, c.x);
        #pragma unroll
        for (int k=0;k<4;++k){
            ulonglong2 d2 = *(const ulonglong2*)&sda[i*8 + 2*k];
            ulonglong2 e2 = *(const ulonglong2*)&sdb[i*8 + 2*k];
            ulonglong2 x2 = *(const ulonglong2*)&sxa[i*8 + 2*k];
            ulonglong2 y2 = *(const ulonglong2*)&sxb[i*8 + 2*k];
            ffma2(ud[2*k],   d2.x, Ap); ffma2(ud[2*k],   e2.x, As);
            ffma2(ud[2*k],   x2.x, Bp); ffma2(ud[2*k],   y2.x, Bs);
            ffma2(us[2*k],   d2.x, Cp); ffma2(us[2*k],   e2.x, Cs);
            ffma2(ud[2*k+1], d2.y, Ap); ffma2(ud[2*k+1], e2.y, As);
            ffma2(ud[2*k+1], x2.y, Bp); ffma2(ud[2*k+1], y2.y, Bs);
            ffma2(us[2*k+1], d2.y, Cp); ffma2(us[2*k+1], e2.y, Cs);
        }
    }
    #pragma unroll
    for (int j=0;j<8;++j){
        oud[(long)j*64*CKD + (long)m*CKD + o] = up2(ud[j]);
        ous[(long)j*64*CKD + (long)m*CKD + o] = up2(us[j]);
    }
}

// ---------------- folded inverse DFT (shallow): precomputed tables, parity split ----------------
__global__ void __launch_bounds__(256) k_idft(long uoff, long twoff, int n, int l){
    __shared__ ulonglong2 tab[64*16];
    __shared__ ull stash[16*128];
    int tck = threadIdx.x & 63;
    int parity = (threadIdx.x >> 6) & 1;
    int sub = threadIdx.x >> 7;
    int b  = blockIdx.y;
    int n2 = n >> 1;
    int tb = blockIdx.x * 16;
    const ulonglong2* itw = g_ftw + twoff;
    for (int q = threadIdx.x; q < l*16; q += 256){
        int m = q >> 4, tp = q & 15;
        int t = tb + tp;
        ulonglong2 val = make_ulonglong2(0ull, 0ull);
        if (t < n2) val = itw[(long)m*n2 + t];
        tab[q] = val;
    }
    __syncthreads();
    const float4* pod4 = (const float4*)(g_oud + (long)b*64*CKD) + tck;
    const float4* pos4 = (const float4*)(g_ous + (long)b*64*CKD) + tck;
    ull acc[16];
    #pragma unroll
    for (int i=0;i<16;++i) acc[i]=0ull;
    int mcount = (l - parity + 1) >> 1;
    if (mcount > 0){
        float4 yd = pod4[(long)parity*64];
        float4 ys = pos4[(long)parity*64];
        for (int k=0; k<mcount; ++k){
            int m = parity + 2*k;
            float4 ydn = make_float4(0,0,0,0), ysn = make_float4(0,0,0,0);
            if (k+1 < mcount){
                ydn = pod4[(long)(m+2)*64];
                ysn = pos4[(long)(m+2)*64];
            }
            ull re0 = pk2(yd.x, ys.x), im0 = pk2(yd.y, ys.y);
            ull re1 = pk2(yd.z, ys.z), im1 = pk2(yd.w, ys.w);
            const ulonglong2* row = &tab[m*16 + sub*8];
            #pragma unroll
            for (int tp=0; tp<8; ++tp){
                ulonglong2 t2 = row[tp];
                ffma2(acc[tp*2],   re0, t2.x);
                ffma2(acc[tp*2],   im0, t2.y);
                ffma2(acc[tp*2+1], re1, t2.x);
                ffma2(acc[tp*2+1], im1, t2.y);
            }
            yd = ydn; ys = ysn;
        }
    }
    if (parity == 0){
        #pragma unroll
        for (int i=0;i<16;++i) stash[i*128 + sub*64 + tck] = acc[i];
    }
    __syncthreads();
    if (parity == 1){
        float* pud = g_ud + uoff + (long)b*n*CKD + 2*tck;
        float* pus = g_us + uoff + (long)b*n*CKD + 2*tck;
        #pragma unroll
        for (int tp=0; tp<8; ++tp){
            int t = tb + sub*8 + tp;
            if (t < n2){
                float2 E0 = up2(stash[(tp*2)*128   + sub*64 + tck]);
                float2 E1 = up2(stash[(tp*2+1)*128 + sub*64 + tck]);
                float2 O0 = up2(acc[tp*2]), O1 = up2(acc[tp*2+1]);
                *(float2*)(pud + (long)t*CKD)      = make_float2(E0.x+O0.x, E1.x+O1.x);
                *(float2*)(pus + (long)t*CKD)      = make_float2(E0.y+O0.y, E1.y+O1.y);
                *(float2*)(pud + (long)(t+n2)*CKD) = make_float2(E0.x-O0.x, E1.x-O1.x);
                *(float2*)(pus + (long)(t+n2)*CKD) = make_float2(E0.y-O0.y, E1.y-O1.y);
            }
        }
    }
}

// ---------------- batched deep kernels ----------------
__device__ const long DOFFd[7] = {0,131072,196608,229376,245760,253952,258048};

__global__ void __launch_bounds__(128) k_dfdft(){
    __shared__ float vb[64*128];
    int li = blockIdx.x, b = blockIdx.y, src = blockIdx.z;
    int nh = 64 >> li, n2 = nh >> 1, lm = n2 + 1;
    int stride = 64 << li;
    int ck = threadIdx.x;
    long soff = off_level(6+li);
    const float* v = src ? (g_xs + soff + (long)b*nh*CKD)
                         : (g_d + DOFFd[li] + (long)b*nh*CKD);
    float2* dst = g_part + DEEP_FT_BASE + ((long)(li*16+b)*2 + src)*64*CKD;
    if (n2 == 0){
        dst[ck] = make_float2(v[ck], 0.f);
        return;
    }
    for (int i = ck; i < nh*CKD; i += 128) vb[i] = v[i];
    __syncthreads();
    for (int m = 0; m < lm; ++m){
        float ar = 0.f, ai = 0.f;
        for (int s = 0; s < n2; ++s){
            float v0 = vb[s*CKD + ck], v1 = vb[(s+n2)*CKD + ck];
            float a = (m & 1) ? (v0 - v1) : (v0 + v1);
            float2 t = g_tw[(m*s*stride) & 4095];
            ar = fmaf(a, t.x, ar);
            ai = fmaf(a, t.y, ai);
        }
        dst[(long)m*CKD + ck] = make_float2(ar, ai);
    }
}

__global__ void __launch_bounds__(128) k_dmix(){
    __shared__ __align__(16) ull sda[128*4], sdb[128*4], sxa[128*4], sxb[128*4];
    int g = blockIdx.x;
    int li, m;
    if (g < 33){ li=0; m=g; }
    else if (g < 50){ li=1; m=g-33; }
    else if (g < 59){ li=2; m=g-50; }
    else if (g < 64){ li=3; m=g-59; }
    else if (g < 67){ li=4; m=g-64; }
    else if (g < 69){ li=5; m=g-67; }
    else { li=6; m=g-69; }
    int bg = blockIdx.y;
    int o = threadIdx.x;
    const float2* ftd = g_part + DEEP_FT_BASE + ((long)(li*16 + bg*4)*2 + 0)*64*CKD;
    const float2* ftx = g_part + DEEP_FT_BASE + ((long)(li*16 + bg*4)*2 + 1)*64*CKD;
    float2* oud = g_part + DEEP_OU_BASE + ((long)(li*16 + bg*4)*2 + 0)*64*CKD;
    float2* ous = g_part + DEEP_OU_BASE + ((long)(li*16 + bg*4)*2 + 1)*64*CKD;
    #pragma unroll
    for (int j=0;j<4;++j){
        float2 f = ftd[(long)j*2*64*CKD + (long)m*CKD + o];
        sda[o*4+j] = pk2(f.x, f.x);
        sdb[o*4+j] = pk2(-f.y, f.y);
        float2 gg = ftx[(long)j*2*64*CKD + (long)m*CKD + o];
        sxa[o*4+j] = pk2(gg.x, gg.x);
        sxb[o*4+j] = pk2(-gg.y, gg.y);
    }
    __syncthreads();
    const float2* wA = g_wt + (long)m*16384 + o;
    const float2* wB = wA + (long)64*16384;
    const float2* wC = wB + (long)64*16384;
    ull ud[4], us[4];
    #pragma unroll
    for (int j=0;j<4;++j){ ud[j]=0ull; us[j]=0ull; }
    #pragma unroll 2
    for (int i=0;i<128;++i){
        float2 a = wA[(long)i*CKD];
        float2 b = wB[(long)i*CKD];
        float2 c = wC[(long)i*CKD];
        ull Ap = pk2(a.x, a.y), As = pk2(a.y, a.x);
        ull Bp = pk2(b.x, b.y), Bs = pk2(b.y, b.x);
        ull Cp = pk2(c.x, c.y), Cs = pk2(c.y, c.x);
        ulonglong2 d01 = *(const ulonglong2*)&sda[i*4];
        ulonglong2 d23 = *(const ulonglong2*)&sda[i*4+2];
        ulonglong2 e01 = *(const ulonglong2*)&sdb[i*4];
        ulonglong2 e23 = *(const ulonglong2*)&sdb[i*4+2];
        ulonglong2 x01 = *(const ulonglong2*)&sxa[i*4];
        ulonglong2 x23 = *(const ulonglong2*)&sxa[i*4+2];
        ulonglong2 y01 = *(const ulonglong2*)&sxb[i*4];
        ulonglong2 y23 = *(const ulonglong2*)&sxb[i*4+2];
        ffma2(ud[0], d01.x, Ap); ffma2(ud[0], e01.x, As);
        ffma2(ud[0], x01.x, Bp); ffma2(ud[0], y01.x, Bs);
        ffma2(us[0], d01.x, Cp); ffma2(us[0], e01.x, Cs);
        ffma2(ud[1], d01.y, Ap); ffma2(ud[1], e01.y, As);
        ffma2(ud[1], x01.y, Bp); ffma2(ud[1], y01.y, Bs);
        ffma2(us[1], d01.y, Cp); ffma2(us[1], e01.y, Cs);
        ffma2(ud[2], d23.x, Ap); ffma2(ud[2], e23.x, As);
        ffma2(ud[2], x23.x, Bp); ffma2(ud[2], y23.x, Bs);
        ffma2(us[2], d23.x, Cp); ffma2(us[2], e23.x, Cs);
        ffma2(ud[3], d23.y, Ap); ffma2(ud[3], e23.y, As);
        ffma2(ud[3], x23.y, Bp); ffma2(ud[3], y23.y, Bs);
        ffma2(us[3], d23.y, Cp); ffma2(us[3], e23.y, Cs);
    }
    #pragma unroll
    for (int j=0;j<4;++j){
        oud[(long)j*2*64*CKD + (long)m*CKD + o] = up2(ud[j]);
        ous[(long)j*2*64*CKD + (long)m*CKD + o] = up2(us[j]);
    }
}

__global__ void __launch_bounds__(128) k_didft(){
    int xb = blockIdx.x;
    int li = (xb < 2) ? 0 : xb - 1;
    int tb = (xb == 1) ? 16 : 0;
    int b = blockIdx.y;
    int nh = 64 >> li, n2 = nh >> 1, lm = n2 + 1;
    int stride = 64 << li;
    float invn = 1.0f / (float)nh;
    int ck = threadIdx.x;
    long soff = off_level(6+li);
    const float2* oud = g_part + DEEP_OU_BASE + ((long)(li*16+b)*2 + 0)*64*CKD;
    const float2* ous = g_part + DEEP_OU_BASE + ((long)(li*16+b)*2 + 1)*64*CKD;
    float* pud = g_ud + soff + (long)b*nh*CKD;
    float* pus = g_us + soff + (long)b*nh*CKD;
    if (n2 == 0){
        pud[ck] = oud[ck].x;
        pus[ck] = ous[ck].x;
        return;
    }
    int tcount = n2 - tb; if (tcount > 16) tcount = 16;
    if (tcount <= 0) return;
    for (int tp = 0; tp < tcount; ++tp){
        int t = tb + tp;
        float eu=0.f, ou=0.f, es=0.f, os=0.f;
        for (int m = 0; m < lm; ++m){
            float2 y = oud[(long)m*CKD + ck];
            float2 z = ous[(long)m*CKD + ck];
            float2 e = g_tw[(m*t*stride) & 4095];
            float sc = ((m==0) || (2*m==nh)) ? invn : 2.f*invn;
            float vu = sc*(y.x*e.x + y.y*e.y);
            float vs = sc*(z.x*e.x + z.y*e.y);
            if (m & 1){ ou += vu; os += vs; } else { eu += vu; es += vs; }
        }
        pud[(long)t*CKD + ck]      = eu + ou;
        pus[(long)t*CKD + ck]      = es + os;
        pud[(long)(t+n2)*CKD + ck] = eu - ou;
        pus[(long)(t+n2)*CKD + ck] = es - os;
    }
}

// ---------------- LayerNorm + exact GELU ----------------
__global__ void k_lngelu(const float* __restrict__ w, const float* __restrict__ bia, long off){
    int b = blockIdx.x, t = threadIdx.x;
    __shared__ float rs[8];
    float v = g_xs[off + (long)b*CKD + t];
    float s1 = v, s2 = v*v;
    #pragma unroll
    for (int o=16; o; o>>=1){
        s1 += __shfl_xor_sync(0xffffffffu, s1, o);
        s2 += __shfl_xor_sync(0xffffffffu, s2, o);
    }
    if ((t & 31) == 0){ rs[t>>5] = s1; rs[4+(t>>5)] = s2; }
    __syncthreads();
    float m1 = (rs[0]+rs[1]+rs[2]+rs[3]) * (1.0f/128.0f);
    float m2 = (rs[4]+rs[5]+rs[6]+rs[7]) * (1.0f/128.0f);
    float var = m2 - m1*m1;
    float xn = (v - m1) * rsqrtf(var + 1e-5f) * w[t] + bia[t];
    float ge = 0.5f * xn * (1.0f + erff(xn * 0.70710678118654752f));
    g_xs[off + (long)b*CKD + t] = ge;
}

// ---------------- host ----------------
extern "C" void kernel_launch(void* const* d_in, const int* in_sizes, int n_in,
                              void* d_out, int out_size) {
    const float* x   = (const float*)d_in[0];
    const float* Awr = (const float*)d_in[1];
    const float* Awi = (const float*)d_in[2];
    const float* Bwr = (const float*)d_in[3];
    const float* Bwi = (const float*)d_in[4];
    const float* Cwr = (const float*)d_in[5];
    const float* Cwi = (const float*)d_in[6];
    const float* lnw = (const float*)d_in[7];
    const float* lnb = (const float*)d_in[8];
    const float* ecs = (const float*)d_in[9];
    const float* ecd = (const float*)d_in[10];
    const float* rce = (const float*)d_in[11];
    const float* rco = (const float*)d_in[12];
    float* out = (float*)d_out;

    static const int NH[13]  = {4096,2048,1024,512,256,128,64,32,16,8,4,2,1};
    static const int LM[13]  = {64,64,64,64,64,64,33,17,9,5,3,2,1};
    static const int SSP[6]  = {16,16,8,4,2,1};
    static const long DOFFh[7] = {0,131072,196608,229376,245760,253952,258048};
    static const long TWOFF[6] = {0, 196608, 294912, 344064, 368640, 380928};
    long OFF[13];
    OFF[0] = 0;
    for (int l=1; l<13; ++l) OFF[l] = OFF[l-1] + (long)16*NH[l-1]*128;

    k_base<<<16, 256>>>();
    k_tw_all<<<(387072+255)/256, 256>>>();
    long wthr = (long)3*64*128*128;
    k_wtrans<<<(unsigned)((wthr+255)/256), 256>>>(Awr, Awi, Bwr, Bwi, Cwr, Cwi);

    // shallow levels 0..5
    for (int l=0; l<6; ++l){
        int nh = NH[l], lm = LM[l], ssp = SSP[l];
        int n2 = nh >> 1;
        long nthr = (long)16*nh*16;
        unsigned blk = (unsigned)((nthr + 255) / 256);
        k_decompose<<<blk, 256>>>(l==0 ? x : (const float*)0, l ? OFF[l-1] : 0,
                                  OFF[l], 0L, ecs, ecd, nh);
        dim3 gf((lm+15)/16, ssp, 32);
        k_fdft<<<gf, 128>>>(OFF[l], TWOFF[l], ssp>1 ? 1 : 0, nh, lm);
        if (ssp > 1){
            unsigned rb = (unsigned)(((long)16*lm*128 + 255)/256);
            k_ftred<<<dim3(rb, 2), 256>>>(lm, ssp);
        }
        k_mix<<<dim3(lm, 2), 128>>>(lm);
        int gx = (n2 + 15)/16;
        k_idft<<<dim3(gx, 16), 256>>>(OFF[l], TWOFF[l] + (long)32*n2, nh, lm);
    }

    // deep decompose chain (levels 6..12)
    for (int l=6; l<13; ++l){
        int nh = NH[l];
        long nthr = (long)16*nh*16;
        unsigned blk = (unsigned)((nthr + 255) / 256);
        k_decompose<<<blk, 256>>>((const float*)0, OFF[l-1], OFF[l], DOFFh[l-6],
                                  ecs, ecd, nh);
    }
    // batched deep spectral path
    k_dfdft<<<dim3(7,16,2), 128>>>();
    k_dmix<<<dim3(70,4), 128>>>();
    k_didft<<<dim3(8,16), 128>>>();

    k_lngelu<<<16, 128>>>(lnw, lnb, OFF[12]);

    // deep recon chain 12..6
    for (int l=12; l>=6; --l){
        int nh = NH[l];
        long nthr = (long)16*nh*16;
        unsigned blk = (unsigned)((nthr + 255) / 256);
        k_recon<<<blk, 256>>>(OFF[l], OFF[l], (float*)0, OFF[l-1], rce, rco, nh);
    }
    // shallow recon 5..0
    for (int l=5; l>=0; --l){
        int nh = NH[l];
        long nthr = (long)16*nh*16;
        unsigned blk = (unsigned)((nthr + 255) / 256);
        k_recon<<<blk, 256>>>(OFF[l], OFF[l],
                              l ? (float*)0 : out, l ? OFF[l-1] : 0,
                              rce, rco, nh);
    }
}

// round 17
// speedup vs baseline: 1.2195x; 1.1637x over previous
#include <cuda_runtime.h>
#include <cuda_bf16.h>

#define CKD 128
typedef unsigned long long ull;

// ---------------- static scratch ----------------
__device__ float  g_xs[(long)16*8191*128];
__device__ float  g_d [(long)16*8191*128];
__device__ float  g_ud[(long)16*8191*128];
__device__ float  g_us[(long)16*8191*128];
__device__ float2 g_part[(long)2*63*16*8192];
__device__ float2 g_sft[(long)6*2*16*8192];
__device__ float2 g_sou[(long)6*2*16*8192];
__device__ float2 g_wt[(long)3*64*128*128];
__device__ float2 g_tw[4096+64];
__device__ ulonglong2 g_ftw[(long)96*4096];

#define DEEP_FT_BASE 0L
#define DEEP_OU_BASE 1835008L

// shallow level tables
__device__ const int  PCHd[6]   = {0,32,48,56,60,62};
__device__ const long TWOFFd[6] = {0,196608,294912,344064,368640,380928};
__device__ const long DSd[6]    = {0,8388608,12582912,14680064,15728640,16252928};
__device__ const int  TBC[6]    = {0,128,192,224,240,248};
// deep d offsets (after shallow d slices)
__device__ const long DOFFd[7]  = {16515072,16646144,16711680,16744448,16760832,16769024,16773120};

// ---------------- f32x2 helpers ----------------
__device__ __forceinline__ ull pk2(float x, float y){
    ull r; asm("mov.b64 %0, {%1, %2};" : "=l"(r) : "f"(x), "f"(y)); return r;
}
__device__ __forceinline__ float2 up2(ull v){
    float2 r; asm("mov.b64 {%0, %1}, %2;" : "=f"(r.x), "=f"(r.y) : "l"(v)); return r;
}
__device__ __forceinline__ void ffma2(ull &acc, ull a, ull b){
    asm("fma.rn.f32x2 %0, %1, %2, %0;" : "+l"(acc) : "l"(a), "l"(b));
}
__device__ __forceinline__ long off_level(int l){
    long o = 0; int nhf = 4096;
    for (int i=0;i<l;++i){ o += (long)16*nhf*128; nhf >>= 1; }
    return o;
}
__device__ __forceinline__ float2 twid(int r){
    float sn, cs;
    sincospif((float)r * (-1.0f/2048.0f), &sn, &cs);
    return make_float2(cs, sn);
}

// ---------------- base twiddle table (deep kernels) ----------------
__global__ void k_base(){
    int r = blockIdx.x*blockDim.x + threadIdx.x;
    if (r >= 4096) return;
    float s, c;
    sincospif(r/2048.0f, &s, &c);
    g_tw[r] = make_float2(c, -s);
    if (r < 64) g_tw[4096+r] = make_float2(0.f, 0.f);
}

// ---------------- batched packed twiddle tables for shallow levels 0..5 ----------------
__global__ void k_tw_all(){
    const int CUM[7] = {0, 196608, 294912, 344064, 368640, 380928, 387072};
    int idx = blockIdx.x*blockDim.x + threadIdx.x;
    if (idx >= 387072) return;
    int l = 0;
    #pragma unroll
    for (int i=1; i<6; ++i) if (idx >= CUM[i]) l = i;
    int local = idx - CUM[l];
    int n2 = 2048 >> l;
    int stride = 1 << l;
    int n = 4096 >> l;
    float invn = 1.0f / (float)n;
    long base = CUM[l];
    long nf = (long)32*n2;
    if (local < nf){
        int jj = local & 3;
        int r = local >> 2;
        int s = r % n2;
        int gh = r / n2;
        int me = (gh>>1)*16 + (gh&1)*8 + 2*jj;
        int mo = me + 1;
        float2 te = twid((me*s*stride)&4095);
        float2 to = twid((mo*s*stride)&4095);
        g_ftw[base + local] = make_ulonglong2(pk2(te.x,te.y), pk2(to.x,to.y));
    } else {
        int r = local - (int)nf;
        int m = r / n2;
        int t = r - m*n2;
        float2 e = twid((m*t*stride)&4095);
        float sc = (m==0) ? invn : 2.f*invn;
        g_ftw[base + local] = make_ulonglong2(pk2(sc*e.x, sc*e.x), pk2(sc*e.y, sc*e.y));
    }
}

// ---------------- weight transpose ----------------
__global__ void k_wtrans(const float* __restrict__ Ar, const float* __restrict__ Ai,
                         const float* __restrict__ Br, const float* __restrict__ Bi,
                         const float* __restrict__ Cr, const float* __restrict__ Ci){
    long gidx = blockIdx.x*(long)blockDim.x + threadIdx.x;
    const long per = (long)64*128*128;
    if (gidx >= 3*per) return;
    int mat = (int)(gidx / per);
    long idx = gidx - (long)mat*per;
    const float* wr = mat==0 ? Ar : (mat==1 ? Br : Cr);
    const float* wi = mat==0 ? Ai : (mat==1 ? Bi : Ci);
    int m = (int)(idx & 63);
    int o = (int)((idx >> 6) & 127);
    int i = (int)(idx >> 13);
    g_wt[((long)mat*64 + m)*16384 + (long)i*128 + o] = make_float2(wr[idx], wi[idx]);
}

// ---------------- wavelet decompose ----------------
__global__ void __launch_bounds__(256) k_decompose(const float* __restrict__ xext, long xoff,
        long soff, long doff,
        const float* __restrict__ ecs, const float* __restrict__ ecd, int nh){
    __shared__ ull f[128];
    if (threadIdx.x < 128) f[threadIdx.x] = pk2(ecs[threadIdx.x], ecd[threadIdx.x]);
    __syncthreads();
    long idx = blockIdx.x*(long)blockDim.x + threadIdx.x;
    if (idx >= (long)16*nh*16) return;
    int c = (int)(idx & 15);
    long bt = idx >> 4;
    const float* xin = xext ? xext : (g_xs + xoff);
    const float* pe = xin + bt*2*CKD + c*8;
    float4 e0 = *(const float4*)(pe);
    float4 e1 = *(const float4*)(pe+4);
    float4 o0 = *(const float4*)(pe+CKD);
    float4 o1 = *(const float4*)(pe+CKD+4);
    float xa[16] = {e0.x,e0.y,e0.z,e0.w, e1.x,e1.y,e1.z,e1.w,
                    o0.x,o0.y,o0.z,o0.w, o1.x,o1.y,o1.z,o1.w};
    ull acc[8];
    #pragma unroll
    for (int ko=0;ko<8;++ko) acc[ko]=0ull;
    #pragma unroll
    for (int j=0;j<16;++j){
        ull vj = pk2(xa[j], xa[j]);
        #pragma unroll
        for (int ko=0;ko<8;++ko) ffma2(acc[ko], vj, f[j*8+ko]);
    }
    float* ps = g_xs + soff + bt*CKD + c*8;
    float* pd = g_d + doff  + bt*CKD + c*8;
    float2 r0=up2(acc[0]), r1=up2(acc[1]), r2=up2(acc[2]), r3=up2(acc[3]);
    float2 r4=up2(acc[4]), r5=up2(acc[5]), r6=up2(acc[6]), r7=up2(acc[7]);
    *(float4*)ps     = make_float4(r0.x,r1.x,r2.x,r3.x);
    *(float4*)(ps+4) = make_float4(r4.x,r5.x,r6.x,r7.x);
    *(float4*)pd     = make_float4(r0.y,r1.y,r2.y,r3.y);
    *(float4*)(pd+4) = make_float4(r4.y,r5.y,r6.y,r7.y);
}

// ---------------- reconstruction ----------------
__global__ void __launch_bounds__(256) k_recon(long xoff, long uoff,
        float* __restrict__ oext, long ooff,
        const float* __restrict__ rce, const float* __restrict__ rco, int nh){
    __shared__ ull f[128];
    if (threadIdx.x < 128) f[threadIdx.x] = pk2(rce[threadIdx.x], rco[threadIdx.x]);
    __syncthreads();
    long idx = blockIdx.x*(long)blockDim.x + threadIdx.x;
    if (idx >= (long)16*nh*16) return;
    int c = (int)(idx & 15);
    long bt = idx >> 4;
    const float* px = g_xs + xoff + bt*CKD + c*8;
    const float* pu = g_us + uoff + bt*CKD + c*8;
    const float* pw = g_ud + uoff + bt*CKD + c*8;
    float4 a0 = *(const float4*)px,     u0 = *(const float4*)pu;
    float4 a1 = *(const float4*)(px+4), u1 = *(const float4*)(pu+4);
    float4 w0 = *(const float4*)pw,     w1 = *(const float4*)(pw+4);
    float xc[16] = {a0.x+u0.x, a0.y+u0.y, a0.z+u0.z, a0.w+u0.w,
                    a1.x+u1.x, a1.y+u1.y, a1.z+u1.z, a1.w+u1.w,
                    w0.x, w0.y, w0.z, w0.w, w1.x, w1.y, w1.z, w1.w};
    ull acc[8];
    #pragma unroll
    for (int ko=0;ko<8;++ko) acc[ko]=0ull;
    #pragma unroll
    for (int j=0;j<16;++j){
        ull vj = pk2(xc[j], xc[j]);
        #pragma unroll
        for (int ko=0;ko<8;++ko) ffma2(acc[ko], vj, f[j*8+ko]);
    }
    float* po = (oext ? oext : (g_xs + ooff)) + bt*2*CKD + c*8;
    float2 r0=up2(acc[0]), r1=up2(acc[1]), r2=up2(acc[2]), r3=up2(acc[3]);
    float2 r4=up2(acc[4]), r5=up2(acc[5]), r6=up2(acc[6]), r7=up2(acc[7]);
    *(float4*)po         = make_float4(r0.x,r1.x,r2.x,r3.x);
    *(float4*)(po+4)     = make_float4(r4.x,r5.x,r6.x,r7.x);
    *(float4*)(po+CKD)   = make_float4(r0.y,r1.y,r2.y,r3.y);
    *(float4*)(po+CKD+4) = make_float4(r4.y,r5.y,r6.y,r7.y);
}

// ---------------- batched shallow forward DFT: grid (4, 63, 32), block 128 ----------------
#define FDC(VR0, VR1, SL) { \
    float ax = VR0.x+VR1.x, ay = VR0.y+VR1.y; \
    float dx = VR0.x-VR1.x, dy = VR0.y-VR1.y; \
    ull a0 = pk2(ax,ax), a1 = pk2(ay,ay), d0 = pk2(dx,dx), d1 = pk2(dy,dy); \
    const ulonglong2* row_ = base + (SL)*4; \
    _Pragma("unroll") \
    for (int j_=0;j_<4;++j_){ \
        ulonglong2 t_ = row_[j_]; \
        ffma2(acc[j_*4+0], a0, t_.x); \
        ffma2(acc[j_*4+1], a1, t_.x); \
        ffma2(acc[j_*4+2], d0, t_.y); \
        ffma2(acc[j_*4+3], d1, t_.y); \
    } }

__global__ void __launch_bounds__(128) k_fdft(){
    __shared__ ulonglong2 stw[512];
    int tck = threadIdx.x & 63;
    int h   = threadIdx.x >> 6;
    int y = blockIdx.y;
    int l = 0;
    #pragma unroll
    for (int i=1; i<6; ++i) if (y >= PCHd[i]) l = i;
    int chunk = y - PCHd[l];
    int n = 4096 >> l, n2 = n >> 1;
    int src = blockIdx.z >> 4;
    int b   = blockIdx.z & 15;
    const float* vsrc = src ? (g_xs + DSd[l]) : (g_d + DSd[l]);
    int s0 = chunk * 64;
    const float2* p2 = (const float2*)(vsrc + ((long)b*n + s0)*CKD) + tck;
    const float2* q2 = p2 + (long)n2*64;
    const ulonglong2* tw0 = g_ftw + TWOFFd[l] + ((long)blockIdx.x*2)*n2*4;
    ull acc[16];
    #pragma unroll
    for (int i=0;i<16;++i) acc[i]=0ull;

    for (int e = threadIdx.x; e < 512; e += 128){
        int jj = e & 3, sl = (e >> 2) & 63, eh = e >> 8;
        stw[(eh*64 + sl)*4 + jj] = tw0[((long)eh*n2 + (s0+sl))*4 + jj];
    }
    __syncthreads();
    const ulonglong2* base = &stw[h*256];
    {
        float2 r0[4], r1[4], u0[4], u1[4];
        #pragma unroll
        for (int i=0;i<4;++i){
            r0[i] = p2[(long)i*64];
            r1[i] = q2[(long)i*64];
        }
        for (int g=0; g<16; g+=2){
            #pragma unroll
            for (int i=0;i<4;++i){
                u0[i] = p2[(long)((g+1)*4+i)*64];
                u1[i] = q2[(long)((g+1)*4+i)*64];
            }
            #pragma unroll
            for (int i=0;i<4;++i) FDC(r0[i], r1[i], g*4+i);
            if (g+2 < 16){
                #pragma unroll
                for (int i=0;i<4;++i){
                    r0[i] = p2[(long)((g+2)*4+i)*64];
                    r1[i] = q2[(long)((g+2)*4+i)*64];
                }
            }
            #pragma unroll
            for (int i=0;i<4;++i) FDC(u0[i], u1[i], (g+1)*4+i);
        }
    }
    float2* dst = g_part + ((long)(src*63 + y)*16 + b)*8192;
    int m0 = blockIdx.x * 16;
    #pragma unroll
    for (int j=0;j<4;++j){
        int me = m0 + 8*h + 2*j;
        {
            float2 c0 = up2(acc[j*4+0]), c1 = up2(acc[j*4+1]);
            *(float4*)((float*)(dst + (long)me*CKD + 2*tck)) = make_float4(c0.x,c0.y,c1.x,c1.y);
        }
        {
            float2 c0 = up2(acc[j*4+2]), c1 = up2(acc[j*4+3]);
            *(float4*)((float*)(dst + (long)(me+1)*CKD + 2*tck)) = make_float4(c0.x,c0.y,c1.x,c1.y);
        }
    }
}

// ---------------- batched reduce: grid (512, 6, 2), block 256 ----------------
__global__ void k_ftred(){
    int l = blockIdx.y, src = blockIdx.z;
    int ssp = 32 >> l;
    long e = blockIdx.x*(long)256 + threadIdx.x;   // 0..131071
    int b = (int)(e >> 13);
    int rem = (int)(e & 8191);
    float2 a = make_float2(0.f, 0.f);
    for (int sp=0; sp<ssp; ++sp){
        float2 p = g_part[((long)(src*63 + PCHd[l] + sp)*16 + b)*8192 + rem];
        a.x += p.x; a.y += p.y;
    }
    g_sft[((long)(l*2 + src)*16 + b)*8192 + rem] = a;
}

// ---------------- batched mode mixing: grid (64, 4, 6), block 128 ----------------
__global__ void __launch_bounds__(128) k_mix(){
    __shared__ __align__(16) ull sda[128*4], sdb[128*4], sxa[128*4], sxb[128*4];
    int o = threadIdx.x;
    int m = blockIdx.x;
    int bg = blockIdx.y;
    int l = blockIdx.z;
    const float2* ftd = g_sft + ((long)(l*2+0)*16 + bg*4)*8192;
    const float2* ftx = g_sft + ((long)(l*2+1)*16 + bg*4)*8192;
    float2* oud = g_sou + ((long)(l*2+0)*16 + bg*4)*8192;
    float2* ous = g_sou + ((long)(l*2+1)*16 + bg*4)*8192;
    #pragma unroll
    for (int j=0;j<4;++j){
        float2 f = ftd[(long)j*8192 + (long)m*CKD + o];
        sda[o*4+j] = pk2(f.x, f.x);
        sdb[o*4+j] = pk2(-f.y, f.y);
        float2 g = ftx[(long)j*8192 + (long)m*CKD + o];
        sxa[o*4+j] = pk2(g.x, g.x);
        sxb[o*4+j] = pk2(-g.y, g.y);
    }
    __syncthreads();
    const float2* wA = g_wt + (long)m*16384 + o;
    const float2* wB = wA + (long)64*16384;
    const float2* wC = wB + (long)64*16384;
    ull ud[4], us[4];
    #pragma unroll
    for (int j=0;j<4;++j){ ud[j]=0ull; us[j]=0ull; }
    #pragma unroll 2
    for (int i=0;i<128;++i){
        float2 a = wA[(long)i*CKD];
        float2 b = wB[(long)i*CKD];
        float2 c = wC[(long)i*CKD];
        ull Ap = pk2(a.x, a.y), As = pk2(a.y, a.x);
        ull Bp = pk2(b.x, b.y), Bs = pk2(b.y, b.x);
        ull Cp = pk2(c.x, c.y), Cs = pk2(c.y, c.x);
        ulonglong2 d01 = *(const ulonglong2*)&sda[i*4];
        ulonglong2 d23 = *(const ulonglong2*)&sda[i*4+2];
        ulonglong2 e01 = *(const ulonglong2*)&sdb[i*4];
        ulonglong2 e23 = *(const ulonglong2*)&sdb[i*4+2];
        ulonglong2 x01 = *(const ulonglong2*)&sxa[i*4];
        ulonglong2 x23 = *(const ulonglong2*)&sxa[i*4+2];
        ulonglong2 y01 = *(const ulonglong2*)&sxb[i*4];
        ulonglong2 y23 = *(const ulonglong2*)&sxb[i*4+2];
        ffma2(ud[0], d01.x, Ap); ffma2(ud[0], e01.x, As);
        ffma2(ud[0], x01.x, Bp); ffma2(ud[0], y01.x, Bs);
        ffma2(us[0], d01.x, Cp); ffma2(us[0], e01.x, Cs);
        ffma2(ud[1], d01.y, Ap); ffma2(ud[1], e01.y, As);
        ffma2(ud[1], x01.y, Bp); ffma2(ud[1], y01.y, Bs);
        ffma2(us[1], d01.y, Cp); ffma2(us[1], e01.y, Cs);
        ffma2(ud[2], d23.x, Ap); ffma2(ud[2], e23.x, As);
        ffma2(ud[2], x23.x, Bp); ffma2(ud[2], y23.x, Bs);
        ffma2(us[2], d23.x, Cp); ffma2(us[2], e23.x, Cs);
        ffma2(ud[3], d23.y, Ap); ffma2(ud[3], e23.y, As);
        ffma2(ud[3], x23.y, Bp); ffma2(ud[3], y23.y, Bs);
        ffma2(us[3], d23.y, Cp); ffma2(us[3], e23.y, Cs);
    }
    #pragma unroll
    for (int j=0;j<4;++j){
        oud[(long)j*8192 + (long)m*CKD + o] = up2(ud[j]);
        ous[(long)j*8192 + (long)m*CKD + o] = up2(us[j]);
    }
}

// ---------------- batched shallow inverse DFT: grid (252, 16), block 256 ----------------
__global__ void __launch_bounds__(256) k_idft(){
    __shared__ ulonglong2 tab[64*16];
    __shared__ ull stash[16*128];
    int tck = threadIdx.x & 63;
    int parity = (threadIdx.x >> 6) & 1;
    int sub = threadIdx.x >> 7;
    int xb = blockIdx.x;
    int l = 0;
    #pragma unroll
    for (int i=1; i<6; ++i) if (xb >= TBC[i]) l = i;
    int tb = (xb - TBC[l]) * 16;
    int b = blockIdx.y;
    int n = 4096 >> l, n2 = n >> 1;
    const ulonglong2* itw = g_ftw + TWOFFd[l] + (long)32*n2;
    for (int q = threadIdx.x; q < 64*16; q += 256){
        int m = q >> 4, tp = q & 15;
        tab[q] = itw[(long)m*n2 + tb + tp];
    }
    __syncthreads();
    const float4* pod4 = (const float4*)(g_sou + ((long)(l*2+0)*16 + b)*8192) + tck;
    const float4* pos4 = (const float4*)(g_sou + ((long)(l*2+1)*16 + b)*8192) + tck;
    ull acc[16];
    #pragma unroll
    for (int i=0;i<16;++i) acc[i]=0ull;
    {
        float4 yd = pod4[(long)parity*64];
        float4 ys = pos4[(long)parity*64];
        for (int k=0; k<32; ++k){
            int m = parity + 2*k;
            float4 ydn = make_float4(0,0,0,0), ysn = make_float4(0,0,0,0);
            if (k+1 < 32){
                ydn = pod4[(long)(m+2)*64];
                ysn = pos4[(long)(m+2)*64];
            }
            ull re0 = pk2(yd.x, ys.x), im0 = pk2(yd.y, ys.y);
            ull re1 = pk2(yd.z, ys.z), im1 = pk2(yd.w, ys.w);
            const ulonglong2* row = &tab[m*16 + sub*8];
            #pragma unroll
            for (int tp=0; tp<8; ++tp){
                ulonglong2 t2 = row[tp];
                ffma2(acc[tp*2],   re0, t2.x);
                ffma2(acc[tp*2],   im0, t2.y);
                ffma2(acc[tp*2+1], re1, t2.x);
                ffma2(acc[tp*2+1], im1, t2.y);
            }
            yd = ydn; ys = ysn;
        }
    }
    if (parity == 0){
        #pragma unroll
        for (int i=0;i<16;++i) stash[i*128 + sub*64 + tck] = acc[i];
    }
    __syncthreads();
    if (parity == 1){
        float* pud = g_ud + DSd[l] + (long)b*n*CKD + 2*tck;
        float* pus = g_us + DSd[l] + (long)b*n*CKD + 2*tck;
        #pragma unroll
        for (int tp=0; tp<8; ++tp){
            int t = tb + sub*8 + tp;
            float2 E0 = up2(stash[(tp*2)*128   + sub*64 + tck]);
            float2 E1 = up2(stash[(tp*2+1)*128 + sub*64 + tck]);
            float2 O0 = up2(acc[tp*2]), O1 = up2(acc[tp*2+1]);
            *(float2*)(pud + (long)t*CKD)      = make_float2(E0.x+O0.x, E1.x+O1.x);
            *(float2*)(pus + (long)t*CKD)      = make_float2(E0.y+O0.y, E1.y+O1.y);
            *(float2*)(pud + (long)(t+n2)*CKD) = make_float2(E0.x-O0.x, E1.x-O1.x);
            *(float2*)(pus + (long)(t+n2)*CKD) = make_float2(E0.y-O0.y, E1.y-O1.y);
        }
    }
}

// ---------------- batched deep kernels ----------------
__global__ void __launch_bounds__(128) k_dfdft(){
    __shared__ float vb[64*128];
    int li = blockIdx.x, b = blockIdx.y, src = blockIdx.z;
    int nh = 64 >> li, n2 = nh >> 1, lm = n2 + 1;
    int stride = 64 << li;
    int ck = threadIdx.x;
    long soff = off_level(6+li);
    const float* v = src ? (g_xs + soff + (long)b*nh*CKD)
                         : (g_d + DOFFd[li] + (long)b*nh*CKD);
    float2* dst = g_part + DEEP_FT_BASE + ((long)(li*16+b)*2 + src)*64*CKD;
    if (n2 == 0){
        dst[ck] = make_float2(v[ck], 0.f);
        return;
    }
    for (int i = ck; i < nh*CKD; i += 128) vb[i] = v[i];
    __syncthreads();
    for (int m = 0; m < lm; ++m){
        float ar = 0.f, ai = 0.f;
        for (int s = 0; s < n2; ++s){
            float v0 = vb[s*CKD + ck], v1 = vb[(s+n2)*CKD + ck];
            float a = (m & 1) ? (v0 - v1) : (v0 + v1);
            float2 t = g_tw[(m*s*stride) & 4095];
            ar = fmaf(a, t.x, ar);
            ai = fmaf(a, t.y, ai);
        }
        dst[(long)m*CKD + ck] = make_float2(ar, ai);
    }
}

__global__ void __launch_bounds__(128) k_dmix(){
    __shared__ __align__(16) ull sda[128*4], sdb[128*4], sxa[128*4], sxb[128*4];
    int g = blockIdx.x;
    int li, m;
    if (g < 33){ li=0; m=g; }
    else if (g < 50){ li=1; m=g-33; }
    else if (g < 59){ li=2; m=g-50; }
    else if (g < 64){ li=3; m=g-59; }
    else if (g < 67){ li=4; m=g-64; }
    else if (g < 69){ li=5; m=g-67; }
    else { li=6; m=g-69; }
    int bg = blockIdx.y;
    int o = threadIdx.x;
    const float2* ftd = g_part + DEEP_FT_BASE + ((long)(li*16 + bg*4)*2 + 0)*64*CKD;
    const float2* ftx = g_part + DEEP_FT_BASE + ((long)(li*16 + bg*4)*2 + 1)*64*CKD;
    float2* oud = g_part + DEEP_OU_BASE + ((long)(li*16 + bg*4)*2 + 0)*64*CKD;
    float2* ous = g_part + DEEP_OU_BASE + ((long)(li*16 + bg*4)*2 + 1)*64*CKD;
    #pragma unroll
    for (int j=0;j<4;++j){
        float2 f = ftd[(long)j*2*64*CKD + (long)m*CKD + o];
        sda[o*4+j] = pk2(f.x, f.x);
        sdb[o*4+j] = pk2(-f.y, f.y);
        float2 gg = ftx[(long)j*2*64*CKD + (long)m*CKD + o];
        sxa[o*4+j] = pk2(gg.x, gg.x);
        sxb[o*4+j] = pk2(-gg.y, gg.y);
    }
    __syncthreads();
    const float2* wA = g_wt + (long)m*16384 + o;
    const float2* wB = wA + (long)64*16384;
    const float2* wC = wB + (long)64*16384;
    ull ud[4], us[4];
    #pragma unroll
    for (int j=0;j<4;++j){ ud[j]=0ull; us[j]=0ull; }
    #pragma unroll 2
    for (int i=0;i<128;++i){
        float2 a = wA[(long)i*CKD];
        float2 b = wB[(long)i*CKD];
        float2 c = wC[(long)i*CKD];
        ull Ap = pk2(a.x, a.y), As = pk2(a.y, a.x);
        ull Bp = pk2(b.x, b.y), Bs = pk2(b.y, b.x);
        ull Cp = pk2(c.x, c.y), Cs = pk2(c.y, c.x);
        ulonglong2 d01 = *(const ulonglong2*)&sda[i*4];
        ulonglong2 d23 = *(const ulonglong2*)&sda[i*4+2];
        ulonglong2 e01 = *(const ulonglong2*)&sdb[i*4];
        ulonglong2 e23 = *(const ulonglong2*)&sdb[i*4+2];
        ulonglong2 x01 = *(const ulonglong2*)&sxa[i*4];
        ulonglong2 x23 = *(const ulonglong2*)&sxa[i*4+2];
        ulonglong2 y01 = *(const ulonglong2*)&sxb[i*4];
        ulonglong2 y23 = *(const ulonglong2*)&sxb[i*4+2];
        ffma2(ud[0], d01.x, Ap); ffma2(ud[0], e01.x, As);
        ffma2(ud[0], x01.x, Bp); ffma2(ud[0], y01.x, Bs);
        ffma2(us[0], d01.x, Cp); ffma2(us[0], e01.x, Cs);
        ffma2(ud[1], d01.y, Ap); ffma2(ud[1], e01.y, As);
        ffma2(ud[1], x01.y, Bp); ffma2(ud[1], y01.y, Bs);
        ffma2(us[1], d01.y, Cp); ffma2(us[1], e01.y, Cs);
        ffma2(ud[2], d23.x, Ap); ffma2(ud[2], e23.x, As);
        ffma2(ud[2], x23.x, Bp); ffma2(ud[2], y23.x, Bs);
        ffma2(us[2], d23.x, Cp); ffma2(us[2], e23.x, Cs);
        ffma2(ud[3], d23.y, Ap); ffma2(ud[3], e23.y, As);
        ffma2(ud[3], x23.y, Bp); ffma2(ud[3], y23.y, Bs);
        ffma2(us[3], d23.y, Cp); ffma2(us[3], e23.y, Cs);
    }
    #pragma unroll
    for (int j=0;j<4;++j){
        oud[(long)j*2*64*CKD + (long)m*CKD + o] = up2(ud[j]);
        ous[(long)j*2*64*CKD + (long)m*CKD + o] = up2(us[j]);
    }
}

__global__ void __launch_bounds__(128) k_didft(){
    int xb = blockIdx.x;
    int li = (xb < 2) ? 0 : xb - 1;
    int tb = (xb == 1) ? 16 : 0;
    int b = blockIdx.y;
    int nh = 64 >> li, n2 = nh >> 1, lm = n2 + 1;
    int stride = 64 << li;
    float invn = 1.0f / (float)nh;
    int ck = threadIdx.x;
    long soff = off_level(6+li);
    const float2* oud = g_part + DEEP_OU_BASE + ((long)(li*16+b)*2 + 0)*64*CKD;
    const float2* ous = g_part + DEEP_OU_BASE + ((long)(li*16+b)*2 + 1)*64*CKD;
    float* pud = g_ud + soff + (long)b*nh*CKD;
    float* pus = g_us + soff + (long)b*nh*CKD;
    if (n2 == 0){
        pud[ck] = oud[ck].x;
        pus[ck] = ous[ck].x;
        return;
    }
    int tcount = n2 - tb; if (tcount > 16) tcount = 16;
    if (tcount <= 0) return;
    for (int tp = 0; tp < tcount; ++tp){
        int t = tb + tp;
        float eu=0.f, ou=0.f, es=0.f, os=0.f;
        for (int m = 0; m < lm; ++m){
            float2 y = oud[(long)m*CKD + ck];
            float2 z = ous[(long)m*CKD + ck];
            float2 e = g_tw[(m*t*stride) & 4095];
            float sc = ((m==0) || (2*m==nh)) ? invn : 2.f*invn;
            float vu = sc*(y.x*e.x + y.y*e.y);
            float vs = sc*(z.x*e.x + z.y*e.y);
            if (m & 1){ ou += vu; os += vs; } else { eu += vu; es += vs; }
        }
        pud[(long)t*CKD + ck]      = eu + ou;
        pus[(long)t*CKD + ck]      = es + os;
        pud[(long)(t+n2)*CKD + ck] = eu - ou;
        pus[(long)(t+n2)*CKD + ck] = es - os;
    }
}

// ---------------- LayerNorm + exact GELU ----------------
__global__ void k_lngelu(const float* __restrict__ w, const float* __restrict__ bia, long off){
    int b = blockIdx.x, t = threadIdx.x;
    __shared__ float rs[8];
    float v = g_xs[off + (long)b*CKD + t];
    float s1 = v, s2 = v*v;
    #pragma unroll
    for (int o=16; o; o>>=1){
        s1 += __shfl_xor_sync(0xffffffffu, s1, o);
        s2 += __shfl_xor_sync(0xffffffffu, s2, o);
    }
    if ((t & 31) == 0){ rs[t>>5] = s1; rs[4+(t>>5)] = s2; }
    __syncthreads();
    float m1 = (rs[0]+rs[1]+rs[2]+rs[3]) * (1.0f/128.0f);
    float m2 = (rs[4]+rs[5]+rs[6]+rs[7]) * (1.0f/128.0f);
    float var = m2 - m1*m1;
    float xn = (v - m1) * rsqrtf(var + 1e-5f) * w[t] + bia[t];
    float ge = 0.5f * xn * (1.0f + erff(xn * 0.70710678118654752f));
    g_xs[off + (long)b*CKD + t] = ge;
}

// ---------------- host ----------------
extern "C" void kernel_launch(void* const* d_in, const int* in_sizes, int n_in,
                              void* d_out, int out_size) {
    const float* x   = (const float*)d_in[0];
    const float* Awr = (const float*)d_in[1];
    const float* Awi = (const float*)d_in[2];
    const float* Bwr = (const float*)d_in[3];
    const float* Bwi = (const float*)d_in[4];
    const float* Cwr = (const float*)d_in[5];
    const float* Cwi = (const float*)d_in[6];
    const float* lnw = (const float*)d_in[7];
    const float* lnb = (const float*)d_in[8];
    const float* ecs = (const float*)d_in[9];
    const float* ecd = (const float*)d_in[10];
    const float* rce = (const float*)d_in[11];
    const float* rco = (const float*)d_in[12];
    float* out = (float*)d_out;

    static const int NH[13]  = {4096,2048,1024,512,256,128,64,32,16,8,4,2,1};
    static const long DSh[6] = {0,8388608,12582912,14680064,15728640,16252928};
    static const long DOFFh[7] = {16515072,16646144,16711680,16744448,16760832,16769024,16773120};
    long OFF[13];
    OFF[0] = 0;
    for (int l=1; l<13; ++l) OFF[l] = OFF[l-1] + (long)16*NH[l-1]*128;

    k_base<<<16, 256>>>();
    k_tw_all<<<(387072+255)/256, 256>>>();
    long wthr = (long)3*64*128*128;
    k_wtrans<<<(unsigned)((wthr+255)/256), 256>>>(Awr, Awi, Bwr, Bwi, Cwr, Cwi);

    // full decompose chain (levels 0..12)
    for (int l=0; l<13; ++l){
        int nh = NH[l];
        long doff = (l < 6) ? DSh[l] : DOFFh[l-6];
        long nthr = (long)16*nh*16;
        unsigned blk = (unsigned)((nthr + 255) / 256);
        k_decompose<<<blk, 256>>>(l==0 ? x : (const float*)0, l ? OFF[l-1] : 0,
                                  OFF[l], doff, ecs, ecd, nh);
    }

    // batched shallow spectral path (all 6 levels in 4 launches)
    k_fdft<<<dim3(4, 63, 32), 128>>>();
    k_ftred<<<dim3(512, 6, 2), 256>>>();
    k_mix<<<dim3(64, 4, 6), 128>>>();
    k_idft<<<dim3(252, 16), 256>>>();

    // batched deep spectral path
    k_dfdft<<<dim3(7,16,2), 128>>>();
    k_dmix<<<dim3(70,4), 128>>>();
    k_didft<<<dim3(8,16), 128>>>();

    k_lngelu<<<16, 128>>>(lnw, lnb, OFF[12]);

    // recon chains 12..0
    for (int l=12; l>=0; --l){
        int nh = NH[l];
        long nthr = (long)16*nh*16;
        unsigned blk = (unsigned)((nthr + 255) / 256);
        k_recon<<<blk, 256>>>(OFF[l], OFF[l],
                              l ? (float*)0 : out, l ? OFF[l-1] : 0,
                              rce, rco, nh);
    }
}